// round 8
// baseline (speedup 1.0000x reference)
#include <cuda_runtime.h>
#include <cuda_fp16.h>
#include <math.h>
#include <stdint.h>

// Problem constants
#define Bb 2
#define Ss 2048
#define Dd 1024
#define Hh 16
#define Kk 16
#define Dh 64
#define Mrows (Bb * Ss)   // 4096
#define QKVN 3072         // concatenated q|k|v row width

// ---------------- scratch (device globals; no allocation allowed) ------------
__device__ float g_qkv[(size_t)Mrows * QKVN];   // q|k|v concatenated fp32
__device__ float g_h[Mrows * (Dd / 2)];
__device__ float g_imp[Mrows];
__device__ int   g_topk[Bb * Kk];
__device__ unsigned char g_sel[Bb * Ss];

// fp16 buffers
__device__ __half g_a2x[(size_t)Mrows * 2048];   // x:   [hi | lo]
__device__ __half g_aatt[(size_t)Mrows * 1024];  // att hi (written by attention)
__device__ __half g_bqkv[(size_t)QKVN * 1024];   // Wq^T|Wk^T|Wv^T hi
__device__ __half g_boh[(size_t)Dd * 1024];      // Wo^T hi
__device__ __half g_bs1h[(size_t)(Dd / 2) * 1024]; // Ws1^T hi

// ================= helpers ===================================================
__device__ __forceinline__ uint32_t smem_to_u32(const void* p) {
    uint32_t a;
    asm("{ .reg .u64 t; cvta.to.shared.u64 t, %1; cvt.u32.u64 %0, t; }" : "=r"(a) : "l"(p));
    return a;
}
__device__ __forceinline__ void cp_async16(uint32_t dst, const void* src) {
    asm volatile("cp.async.cg.shared.global [%0], [%1], 16;" :: "r"(dst), "l"(src));
}
#define CP_COMMIT() asm volatile("cp.async.commit_group;" ::: "memory")
#define CP_WAIT(n)  asm volatile("cp.async.wait_group %0;" :: "n"(n) : "memory")

__device__ __forceinline__ void ldsm_x4(uint32_t* r, uint32_t addr) {
    asm volatile("ldmatrix.sync.aligned.m8n8.x4.shared.b16 {%0,%1,%2,%3}, [%4];"
        : "=r"(r[0]), "=r"(r[1]), "=r"(r[2]), "=r"(r[3]) : "r"(addr));
}
__device__ __forceinline__ void mma16816(float* d, const uint32_t* a, const uint32_t* b) {
    asm volatile(
        "mma.sync.aligned.m16n8k16.row.col.f32.f16.f16.f32 "
        "{%0,%1,%2,%3}, {%4,%5,%6,%7}, {%8,%9}, {%0,%1,%2,%3};"
        : "+f"(d[0]), "+f"(d[1]), "+f"(d[2]), "+f"(d[3])
        : "r"(a[0]), "r"(a[1]), "r"(a[2]), "r"(a[3]), "r"(b[0]), "r"(b[1]));
}

// ================= conversion kernels ========================================
// fp32 [M,1024] -> fp16 [M, 2048] = [hi | lo]; also zeroes imp[0..4095]
__global__ __launch_bounds__(256) void splitA2_kernel(
    const float* __restrict__ A, __half* __restrict__ A2, float* __restrict__ imp)
{
    int i = blockIdx.x * 256 + threadIdx.x;
    if (i < Mrows) imp[i] = 0.f;
    float a = A[i];
    __half hi = __float2half(a);
    __half lo = __float2half(a - __half2float(hi));
    int row = i >> 10, kcol = i & 1023;
    size_t base = (size_t)row * 2048;
    A2[base + kcol]        = hi;
    A2[base + 1024 + kcol] = lo;
}

// Batched: W[1024,1024] fp32 -> dst[N=1024,1024] fp16 hi, transposed.
// z = 0,1,2 -> bqkv segment; z = 3 -> boh
__global__ __launch_bounds__(256) void splitWh4_kernel(
    const float* __restrict__ Wq, const float* __restrict__ Wk,
    const float* __restrict__ Wv, const float* __restrict__ Wo,
    __half* __restrict__ bqkv, __half* __restrict__ boh)
{
    __shared__ float tile[32][33];
    int z = blockIdx.z;
    const float* W = (z == 0) ? Wq : (z == 1) ? Wk : (z == 2) ? Wv : Wo;
    __half* dst = (z < 3) ? (bqkv + (size_t)z * 1024 * 1024) : boh;
    int tx = threadIdx.x & 31, ty = threadIdx.x >> 5;
    int n0 = blockIdx.x * 32, k0 = blockIdx.y * 32;
#pragma unroll
    for (int j = 0; j < 32; j += 8)
        tile[ty + j][tx] = W[(size_t)(k0 + ty + j) * 1024 + n0 + tx];
    __syncthreads();
#pragma unroll
    for (int j = 0; j < 32; j += 8) {
        int n = ty + j;
        dst[(size_t)(n0 + n) * 1024 + k0 + tx] = __float2half(tile[tx][n]);
    }
}

// W[1024,N] fp32 -> Bo[N,1024] fp16 hi, transposed (for Ws1, N=512)
__global__ __launch_bounds__(256) void splitWh_kernel(
    const float* __restrict__ W, __half* __restrict__ Bo, int N)
{
    __shared__ float tile[32][33];
    int tx = threadIdx.x & 31, ty = threadIdx.x >> 5;
    int n0 = blockIdx.x * 32, k0 = blockIdx.y * 32;
#pragma unroll
    for (int j = 0; j < 32; j += 8)
        tile[ty + j][tx] = W[(size_t)(k0 + ty + j) * N + n0 + tx];
    __syncthreads();
#pragma unroll
    for (int j = 0; j < 32; j += 8) {
        int n = ty + j;
        Bo[(size_t)(n0 + n) * 1024 + k0 + tx] = __float2half(tile[tx][n]);
    }
}

// ================= tensor-core GEMM (mma.sync, fp16) =========================
// mode 0 (hi x hi):   aoff = boff = k
// mode 2 (2-chunk A): aoff = seg*1024 + k, boff = k   (exact A x B_hi)
// If impw != null: epilogue also accumulates imp[row] += sum_col C[row,col]*impw[col]
// CTA tile 128x128, BK=64, XOR swizzle, 256 threads, cp.async double buffer.
#define GT_SMEM_TOTAL 65536

__global__ __launch_bounds__(256) void gemm_tc(
    const __half* __restrict__ A2, const __half* __restrict__ B2,
    const float* __restrict__ bias0, const float* __restrict__ bias1,
    const float* __restrict__ bias2, float* __restrict__ C,
    int ldA, int ldB, int ldC, int iters, int mode, int relu,
    const float* __restrict__ impw, float* __restrict__ impb)
{
    extern __shared__ __align__(1024) char smem[];
    uint32_t sb = smem_to_u32(smem);
    int tid = threadIdx.x, lane = tid & 31, wid = tid >> 5;
    int wm = wid & 3, wn = wid >> 2;
    int bx = blockIdx.x, by = blockIdx.y;

    const __half* Abp = A2 + (size_t)by * 128 * ldA;
    const __half* Bbp = B2 + (size_t)bx * 128 * ldB;

    int r0  = tid >> 3;           // 0..31
    int c16 = tid & 7;            // 0..7
    uint32_t swoff[4];
#pragma unroll
    for (int l = 0; l < 4; l++) {
        uint32_t off = (r0 + l * 32) * 128 + c16 * 16;
        swoff[l] = off ^ ((off >> 3) & 0x70);
    }

    float acc[2][8][4];
#pragma unroll
    for (int mt = 0; mt < 2; mt++)
#pragma unroll
        for (int nt = 0; nt < 8; nt++)
#pragma unroll
            for (int c = 0; c < 4; c++) acc[mt][nt][c] = 0.f;

    uint32_t a_ld[2], b_ld[4];
#pragma unroll
    for (int mt = 0; mt < 2; mt++) {
        int row = wm * 32 + mt * 16 + ((lane >> 3) & 1) * 8 + (lane & 7);
        a_ld[mt] = (uint32_t)(row * 128 + (lane >> 4) * 16);
    }
#pragma unroll
    for (int p = 0; p < 4; p++) {
        int row = wn * 64 + p * 16 + (lane >> 4) * 8 + (lane & 7);
        b_ld[p] = (uint32_t)(row * 128 + ((lane >> 3) & 1) * 16);
    }

    // prologue: iter 0 into buffer 0
#pragma unroll
    for (int l = 0; l < 4; l++) {
        int row = r0 + l * 32;
        cp_async16(sb + swoff[l],         Abp + (size_t)row * ldA + c16 * 8);
        cp_async16(sb + 32768 + swoff[l], Bbp + (size_t)row * ldB + c16 * 8);
    }
    CP_COMMIT();

#pragma unroll 1
    for (int it = 0; it < iters; ++it) {
        int buf = it & 1;
        if (it + 1 < iters) {
            int nx = it + 1;
            int kwithin = (nx & 15) * 64;
            int aoff = (mode == 2) ? ((nx >> 4) * 1024 + kwithin) : kwithin;
            int boff = kwithin;
            const __half* Ak = Abp + aoff;
            const __half* Bk = Bbp + boff;
            uint32_t abase = sb + (buf ^ 1) * 16384;
            uint32_t bbase = sb + 32768 + (buf ^ 1) * 16384;
#pragma unroll
            for (int l = 0; l < 4; l++) {
                int row = r0 + l * 32;
                cp_async16(abase + swoff[l], Ak + (size_t)row * ldA + c16 * 8);
                cp_async16(bbase + swoff[l], Bk + (size_t)row * ldB + c16 * 8);
            }
            CP_COMMIT();
            CP_WAIT(1);
        } else {
            CP_WAIT(0);
        }
        __syncthreads();

        uint32_t ab = sb + buf * 16384;
        uint32_t bbS = sb + 32768 + buf * 16384;
#pragma unroll
        for (int s = 0; s < 4; ++s) {
            uint32_t kb = s * 32;
            uint32_t afr[2][4];
#pragma unroll
            for (int mt = 0; mt < 2; mt++) {
                uint32_t off = a_ld[mt] + kb;
                ldsm_x4(afr[mt], ab + (off ^ ((off >> 3) & 0x70)));
            }
            uint32_t bfr[8][2];
#pragma unroll
            for (int p = 0; p < 4; p++) {
                uint32_t off = b_ld[p] + kb;
                uint32_t r[4];
                ldsm_x4(r, bbS + (off ^ ((off >> 3) & 0x70)));
                bfr[2 * p][0] = r[0]; bfr[2 * p][1] = r[1];
                bfr[2 * p + 1][0] = r[2]; bfr[2 * p + 1][1] = r[3];
            }
#pragma unroll
            for (int mt = 0; mt < 2; mt++)
#pragma unroll
                for (int nt = 0; nt < 8; nt++)
                    mma16816(acc[mt][nt], afr[mt], bfr[nt]);
        }
        __syncthreads();
    }

    // epilogue: bias pointer by 1024-col segment (QKV: bx>>3 in {0,1,2})
    int bsel = bx >> 3;
    const float* bp = (bsel == 0) ? bias0 : (bsel == 1 ? bias1 : bias2);
    int bcol0 = (bx & 7) * 128;

    int g = lane >> 2, t4 = lane & 3;
    float pr[4] = {0.f, 0.f, 0.f, 0.f};   // imp partials: rows r, r+8 per mt
#pragma unroll
    for (int mt = 0; mt < 2; mt++) {
        int row = by * 128 + wm * 32 + mt * 16 + g;
#pragma unroll
        for (int nt = 0; nt < 8; nt++) {
            int coff = wn * 64 + nt * 8 + t4 * 2;
            int col = bx * 128 + coff;
            float b0 = bp[bcol0 + coff], b1 = bp[bcol0 + coff + 1];
            float v0 = acc[mt][nt][0] + b0;
            float v1 = acc[mt][nt][1] + b1;
            float v2 = acc[mt][nt][2] + b0;
            float v3 = acc[mt][nt][3] + b1;
            if (relu) {
                v0 = fmaxf(v0, 0.f); v1 = fmaxf(v1, 0.f);
                v2 = fmaxf(v2, 0.f); v3 = fmaxf(v3, 0.f);
            }
            if (impw) {
                float w20 = impw[col], w21 = impw[col + 1];
                pr[mt * 2 + 0] += v0 * w20 + v1 * w21;
                pr[mt * 2 + 1] += v2 * w20 + v3 * w21;
            }
            *(float2*)(C + (size_t)row * ldC + col)       = make_float2(v0, v1);
            *(float2*)(C + (size_t)(row + 8) * ldC + col) = make_float2(v2, v3);
        }
    }
    if (impw) {
#pragma unroll
        for (int c = 0; c < 4; c++) {
            pr[c] += __shfl_xor_sync(0xffffffffu, pr[c], 1);
            pr[c] += __shfl_xor_sync(0xffffffffu, pr[c], 2);
        }
        if (t4 == 0) {
            int rbase = by * 128 + wm * 32 + g;
            atomicAdd(&impb[rbase],      pr[0]);
            atomicAdd(&impb[rbase + 8],  pr[1]);
            atomicAdd(&impb[rbase + 16], pr[2]);
            atomicAdd(&impb[rbase + 24], pr[3]);
        }
    }
}

// ---------------- per-batch top-16: one warp per batch -----------------------
__global__ __launch_bounds__(32) void topk_kernel(
    const float* __restrict__ imp, int* __restrict__ topk,
    unsigned char* __restrict__ sel)
{
    __shared__ float vals[Ss];
    int b = blockIdx.x, lane = threadIdx.x;
    for (int j = lane; j < Ss; j += 32) {
        vals[j] = imp[b * Ss + j];
        sel[b * Ss + j] = 0;
    }
    __syncwarp();
    for (int it = 0; it < Kk; it++) {
        float m = -INFINITY; int mi = 0;
        for (int j = lane; j < Ss; j += 32) {
            float v = vals[j];
            if (v > m) { m = v; mi = j; }
        }
#pragma unroll
        for (int o = 16; o > 0; o >>= 1) {
            float om = __shfl_xor_sync(0xffffffffu, m, o);
            int   oi = __shfl_xor_sync(0xffffffffu, mi, o);
            if (om > m) { m = om; mi = oi; }
        }
        mi = __shfl_sync(0xffffffffu, mi, 0);
        if (lane == 0) {
            topk[b * Kk + it] = mi;
            sel[b * Ss + mi] = 1;
        }
        vals[mi] = -INFINITY;
        __syncwarp();
    }
}

// ---------------- sparse rows: 8 queries/block, kv+q staged in smem ----------
__global__ __launch_bounds__(256) void attn_sparse(
    const float* __restrict__ qkv, const int* __restrict__ topk,
    const unsigned char* __restrict__ sel, __half* __restrict__ aatt)
{
    __shared__ float k16[16 * 68];
    __shared__ float v16[16 * 68];
    __shared__ float qsm[8 * 64];

    int tid = threadIdx.x, w = tid >> 5, lane = tid & 31;
    int qid0 = blockIdx.x * 8;
    int b = qid0 >> 15;
    int rem = qid0 & 32767;
    int h = rem >> 11;
    int i0 = rem & 2047;
    int i = i0 + w;

    {
        int key = tid >> 4;
        int d0  = (tid & 15) * 4;
        int kj = topk[b * Kk + key];
        const float* kr = qkv + (size_t)(b * Ss + kj) * QKVN + 1024 + h * Dh + d0;
        const float* vr = kr + 1024;
        float4 kv = *(const float4*)kr;
        k16[key * 68 + d0 + 0] = kv.x; k16[key * 68 + d0 + 1] = kv.y;
        k16[key * 68 + d0 + 2] = kv.z; k16[key * 68 + d0 + 3] = kv.w;
        float4 vv = *(const float4*)vr;
        v16[key * 68 + d0 + 0] = vv.x; v16[key * 68 + d0 + 1] = vv.y;
        v16[key * 68 + d0 + 2] = vv.z; v16[key * 68 + d0 + 3] = vv.w;
    }
    {
        const float* qr = qkv + (size_t)(b * Ss + i) * QKVN + h * Dh;
        qsm[w * 64 + lane]      = qr[lane];
        qsm[w * 64 + lane + 32] = qr[lane + 32];
    }
    __syncthreads();

    if (sel[b * Ss + i]) return;

    float score = -INFINITY;
    if (lane < 16) {
        float s = 0.f;
#pragma unroll
        for (int d = 0; d < 64; d++) s += qsm[w * 64 + d] * k16[lane * 68 + d];
        score = s * 0.125f;
    }
    float m = score;
#pragma unroll
    for (int o = 16; o > 0; o >>= 1) m = fmaxf(m, __shfl_xor_sync(0xffffffffu, m, o));
    float e = (lane < 16) ? expf(score - m) : 0.f;
    float ssum = e;
#pragma unroll
    for (int o = 16; o > 0; o >>= 1) ssum += __shfl_xor_sync(0xffffffffu, ssum, o);
    float wgt = e / ssum;

    float acc0 = 0.f, acc1 = 0.f;
#pragma unroll
    for (int j = 0; j < 16; j++) {
        float wj = __shfl_sync(0xffffffffu, wgt, j);
        acc0 = fmaf(wj, v16[j * 68 + lane],      acc0);
        acc1 = fmaf(wj, v16[j * 68 + lane + 32], acc1);
    }
    size_t base = (size_t)(b * Ss + i) * 1024 + h * Dh;
    aatt[base + lane]      = __float2half(acc0);
    aatt[base + lane + 32] = __float2half(acc1);
}

// ---------------- dense rows: flash-style, one block per (b,h) ---------------
#define AD_QS   0
#define AD_KS   4096
#define AD_VS   (4096 + 33792)
#define AD_WS   (4096 + 33792 + 32768)
#define AD_SMEM (4096 + 33792 + 32768 + 8192)

__global__ __launch_bounds__(512) void attn_dense(
    const float* __restrict__ qkv, const int* __restrict__ topk,
    __half* __restrict__ aatt)
{
    extern __shared__ __align__(16) char smraw[];
    float* qs = (float*)(smraw + AD_QS);
    float* ks = (float*)(smraw + AD_KS);
    float* vs = (float*)(smraw + AD_VS);
    float* ws = (float*)(smraw + AD_WS);

    int tid = threadIdx.x, w = tid >> 5, lane = tid & 31;
    int b = blockIdx.x >> 4, h = blockIdx.x & 15;
    int i = topk[b * Kk + w];

    {
        const float* qr = qkv + (size_t)(b * Ss + i) * QKVN + h * Dh;
        qs[w * 64 + lane]      = qr[lane];
        qs[w * 64 + lane + 32] = qr[lane + 32];
    }

    float m_run = -INFINITY, sum_l = 0.f, acc0 = 0.f, acc1 = 0.f;

#pragma unroll 1
    for (int t = 0; t < 16; ++t) {
        __syncthreads();
        {
            int key = tid >> 2;
            int d0  = (tid & 3) * 16;
            const float* kr = qkv + (size_t)(b * Ss + t * 128 + key) * QKVN + 1024 + h * Dh + d0;
            const float* vr = kr + 1024;
#pragma unroll
            for (int u = 0; u < 4; u++) {
                float4 kv = *(const float4*)(kr + u * 4);
                int d = d0 + u * 4;
                ks[(d + 0) * 132 + key] = kv.x;
                ks[(d + 1) * 132 + key] = kv.y;
                ks[(d + 2) * 132 + key] = kv.z;
                ks[(d + 3) * 132 + key] = kv.w;
                *(float4*)(vs + key * 64 + d) = *(const float4*)(vr + u * 4);
            }
        }
        __syncthreads();

        float sc4[4];
        float mloc = -INFINITY;
#pragma unroll
        for (int c = 0; c < 4; c++) {
            int kk = lane + c * 32;
            float s = 0.f;
#pragma unroll
            for (int d = 0; d < 64; d++) s += qs[w * 64 + d] * ks[d * 132 + kk];
            s *= 0.125f;
            sc4[c] = s;
            mloc = fmaxf(mloc, s);
        }
#pragma unroll
        for (int o = 16; o > 0; o >>= 1)
            mloc = fmaxf(mloc, __shfl_xor_sync(0xffffffffu, mloc, o));
        float m_new = fmaxf(m_run, mloc);
        float scale = expf(m_run - m_new);
        acc0 *= scale; acc1 *= scale; sum_l *= scale;
#pragma unroll
        for (int c = 0; c < 4; c++) {
            float wv = expf(sc4[c] - m_new);
            ws[w * 128 + lane + c * 32] = wv;
            sum_l += wv;
        }
        m_run = m_new;
        __syncwarp();
#pragma unroll 4
        for (int j = 0; j < 128; j++) {
            float wj = ws[w * 128 + j];
            acc0 = fmaf(wj, vs[j * 64 + lane],      acc0);
            acc1 = fmaf(wj, vs[j * 64 + lane + 32], acc1);
        }
    }

    float sum = sum_l;
#pragma unroll
    for (int o = 16; o > 0; o >>= 1) sum += __shfl_xor_sync(0xffffffffu, sum, o);
    float inv = 1.f / sum;

    size_t base = (size_t)(b * Ss + i) * 1024 + h * Dh;
    aatt[base + lane]      = __float2half(acc0 * inv);
    aatt[base + lane + 32] = __float2half(acc1 * inv);
}

// ---------------- launcher ---------------------------------------------------
extern "C" void kernel_launch(void* const* d_in, const int* in_sizes, int n_in,
                              void* d_out, int out_size)
{
    const float* x   = (const float*)d_in[0];
    const float* Wq  = (const float*)d_in[1];
    const float* bq  = (const float*)d_in[2];
    const float* Wk  = (const float*)d_in[3];
    const float* bk  = (const float*)d_in[4];
    const float* Wv  = (const float*)d_in[5];
    const float* bv  = (const float*)d_in[6];
    const float* Wo  = (const float*)d_in[7];
    const float* bo  = (const float*)d_in[8];
    const float* Ws1 = (const float*)d_in[9];
    const float* bs1 = (const float*)d_in[10];
    const float* Ws2 = (const float*)d_in[11];
    float* out = (float*)d_out;

    float *qkv, *hbuf, *impb;
    int *tkb; unsigned char *selb;
    __half *a2x, *aatt, *bqkv, *boh, *bs1h;
    cudaGetSymbolAddress((void**)&qkv,  g_qkv);
    cudaGetSymbolAddress((void**)&hbuf, g_h);
    cudaGetSymbolAddress((void**)&impb, g_imp);
    cudaGetSymbolAddress((void**)&tkb,  g_topk);
    cudaGetSymbolAddress((void**)&selb, g_sel);
    cudaGetSymbolAddress((void**)&a2x,  g_a2x);
    cudaGetSymbolAddress((void**)&aatt, g_aatt);
    cudaGetSymbolAddress((void**)&bqkv, g_bqkv);
    cudaGetSymbolAddress((void**)&boh,  g_boh);
    cudaGetSymbolAddress((void**)&bs1h, g_bs1h);

    cudaFuncSetAttribute(gemm_tc, cudaFuncAttributeMaxDynamicSharedMemorySize,
                         GT_SMEM_TOTAL);
    cudaFuncSetAttribute(attn_dense, cudaFuncAttributeMaxDynamicSharedMemorySize,
                         AD_SMEM);

    // conversions (3 launches)
    splitA2_kernel<<<(Mrows * Dd) / 256, 256>>>(x, a2x, impb);
    splitWh4_kernel<<<dim3(32, 32, 4), 256>>>(Wq, Wk, Wv, Wo, bqkv, boh);
    splitWh_kernel<<<dim3(16, 32), 256>>>(Ws1, bs1h, Dd / 2);

    // QKV hi-only GEMM: [4096,1024]x[3072,1024] -> qkv [4096,3072]
    gemm_tc<<<dim3(QKVN / 128, Mrows / 128), 256, GT_SMEM_TOTAL>>>(
        a2x, bqkv, bq, bk, bv, qkv, 2048, 1024, QKVN, 16, 0, 0, nullptr, nullptr);
    // S1 GEMM (2-chunk, relu, fused imp reduction): -> hbuf [4096,512]
    gemm_tc<<<dim3((Dd / 2) / 128, Mrows / 128), 256, GT_SMEM_TOTAL>>>(
        a2x, bs1h, bs1, bs1, bs1, hbuf, 2048, 1024, Dd / 2, 32, 2, 1, Ws2, impb);

    // top-k + attention
    topk_kernel<<<Bb, 32>>>(impb, tkb, selb);
    attn_sparse<<<(Bb * Hh * Ss) / 8, 256>>>(qkv, tkb, selb, aatt);
    attn_dense<<<Bb * Hh, 512, AD_SMEM>>>(qkv, tkb, aatt);

    // output projection (hi x hi)
    gemm_tc<<<dim3(Dd / 128, Mrows / 128), 256, GT_SMEM_TOTAL>>>(
        aatt, boh, bo, bo, bo, out, 1024, 1024, Dd, 16, 0, 0, nullptr, nullptr);
}

// round 9
// speedup vs baseline: 1.6111x; 1.6111x over previous
#include <cuda_runtime.h>
#include <cuda_fp16.h>
#include <math.h>
#include <stdint.h>

// Problem constants
#define Bb 2
#define Ss 2048
#define Dd 1024
#define Hh 16
#define Kk 16
#define Dh 64
#define Mrows (Bb * Ss)   // 4096
#define QKVN 3072         // concatenated q|k|v row width

// ---------------- scratch (device globals; no allocation allowed) ------------
__device__ float g_qkv[(size_t)Mrows * QKVN];   // q|k|v concatenated fp32
__device__ float g_h[Mrows * (Dd / 2)];
__device__ float g_imp[Mrows];
__device__ int   g_topk[Bb * Kk];
__device__ unsigned char g_sel[Bb * Ss];

// fp16 buffers
__device__ __half g_a2x[(size_t)Mrows * 2048];   // x:   [hi | lo]
__device__ __half g_aatt[(size_t)Mrows * 1024];  // att hi (written by attention)
__device__ __half g_bqkv[(size_t)QKVN * 1024];   // Wq^T|Wk^T|Wv^T hi
__device__ __half g_boh[(size_t)Dd * 1024];      // Wo^T hi
__device__ __half g_bs1h[(size_t)(Dd / 2) * 1024]; // Ws1^T hi

// ================= helpers ===================================================
__device__ __forceinline__ uint32_t smem_to_u32(const void* p) {
    uint32_t a;
    asm("{ .reg .u64 t; cvta.to.shared.u64 t, %1; cvt.u32.u64 %0, t; }" : "=r"(a) : "l"(p));
    return a;
}
__device__ __forceinline__ void cp_async16(uint32_t dst, const void* src) {
    asm volatile("cp.async.cg.shared.global [%0], [%1], 16;" :: "r"(dst), "l"(src));
}
#define CP_COMMIT() asm volatile("cp.async.commit_group;" ::: "memory")
#define CP_WAIT(n)  asm volatile("cp.async.wait_group %0;" :: "n"(n) : "memory")

__device__ __forceinline__ void ldsm_x4(uint32_t* r, uint32_t addr) {
    asm volatile("ldmatrix.sync.aligned.m8n8.x4.shared.b16 {%0,%1,%2,%3}, [%4];"
        : "=r"(r[0]), "=r"(r[1]), "=r"(r[2]), "=r"(r[3]) : "r"(addr));
}
__device__ __forceinline__ void mma16816(float* d, const uint32_t* a, const uint32_t* b) {
    asm volatile(
        "mma.sync.aligned.m16n8k16.row.col.f32.f16.f16.f32 "
        "{%0,%1,%2,%3}, {%4,%5,%6,%7}, {%8,%9}, {%0,%1,%2,%3};"
        : "+f"(d[0]), "+f"(d[1]), "+f"(d[2]), "+f"(d[3])
        : "r"(a[0]), "r"(a[1]), "r"(a[2]), "r"(a[3]), "r"(b[0]), "r"(b[1]));
}

// ================= conversion kernels ========================================
// fp32 [M,1024] -> fp16 [M, 2048] = [hi | lo]
__global__ __launch_bounds__(256) void splitA2_kernel(
    const float* __restrict__ A, __half* __restrict__ A2)
{
    int i = blockIdx.x * 256 + threadIdx.x;
    float a = A[i];
    __half hi = __float2half(a);
    __half lo = __float2half(a - __half2float(hi));
    int row = i >> 10, kcol = i & 1023;
    size_t base = (size_t)row * 2048;
    A2[base + kcol]        = hi;
    A2[base + 1024 + kcol] = lo;
}

// Batched: W[1024,1024] fp32 -> dst[1024,1024] fp16 hi, transposed.
// z = 0,1,2 -> bqkv segment; z = 3 -> boh
__global__ __launch_bounds__(256) void splitWh4_kernel(
    const float* __restrict__ Wq, const float* __restrict__ Wk,
    const float* __restrict__ Wv, const float* __restrict__ Wo,
    __half* __restrict__ bqkv, __half* __restrict__ boh)
{
    __shared__ float tile[32][33];
    int z = blockIdx.z;
    const float* W = (z == 0) ? Wq : (z == 1) ? Wk : (z == 2) ? Wv : Wo;
    __half* dst = (z < 3) ? (bqkv + (size_t)z * 1024 * 1024) : boh;
    int tx = threadIdx.x & 31, ty = threadIdx.x >> 5;
    int n0 = blockIdx.x * 32, k0 = blockIdx.y * 32;
#pragma unroll
    for (int j = 0; j < 32; j += 8)
        tile[ty + j][tx] = W[(size_t)(k0 + ty + j) * 1024 + n0 + tx];
    __syncthreads();
#pragma unroll
    for (int j = 0; j < 32; j += 8) {
        int n = ty + j;
        dst[(size_t)(n0 + n) * 1024 + k0 + tx] = __float2half(tile[tx][n]);
    }
}

// W[1024,N] fp32 -> Bo[N,1024] fp16 hi, transposed (for Ws1, N=512)
__global__ __launch_bounds__(256) void splitWh_kernel(
    const float* __restrict__ W, __half* __restrict__ Bo, int N)
{
    __shared__ float tile[32][33];
    int tx = threadIdx.x & 31, ty = threadIdx.x >> 5;
    int n0 = blockIdx.x * 32, k0 = blockIdx.y * 32;
#pragma unroll
    for (int j = 0; j < 32; j += 8)
        tile[ty + j][tx] = W[(size_t)(k0 + ty + j) * N + n0 + tx];
    __syncthreads();
#pragma unroll
    for (int j = 0; j < 32; j += 8) {
        int n = ty + j;
        Bo[(size_t)(n0 + n) * 1024 + k0 + tx] = __float2half(tile[tx][n]);
    }
}

// ================= tensor-core GEMM (mma.sync, fp16) =========================
// mode 0 (hi x hi):   aoff = boff = k
// mode 2 (2-chunk A): aoff = seg*1024 + k, boff = k   (exact A x B_hi)
// CTA tile 128x128, BK=64, XOR swizzle, 256 threads, cp.async double buffer.
// __launch_bounds__(256, 2): cap regs at 128 so 2 CTAs are resident per SM.
#define GT_SMEM_TOTAL 65536

__global__ __launch_bounds__(256, 2) void gemm_tc(
    const __half* __restrict__ A2, const __half* __restrict__ B2,
    const float* __restrict__ bias0, const float* __restrict__ bias1,
    const float* __restrict__ bias2, float* __restrict__ C,
    int ldA, int ldB, int ldC, int iters, int mode, int relu)
{
    extern __shared__ __align__(1024) char smem[];
    uint32_t sb = smem_to_u32(smem);
    int tid = threadIdx.x, lane = tid & 31, wid = tid >> 5;
    int wm = wid & 3, wn = wid >> 2;
    int bx = blockIdx.x, by = blockIdx.y;

    const __half* Abp = A2 + (size_t)by * 128 * ldA;
    const __half* Bbp = B2 + (size_t)bx * 128 * ldB;

    int r0  = tid >> 3;           // 0..31
    int c16 = tid & 7;            // 0..7
    uint32_t swoff[4];
#pragma unroll
    for (int l = 0; l < 4; l++) {
        uint32_t off = (r0 + l * 32) * 128 + c16 * 16;
        swoff[l] = off ^ ((off >> 3) & 0x70);
    }

    float acc[2][8][4];
#pragma unroll
    for (int mt = 0; mt < 2; mt++)
#pragma unroll
        for (int nt = 0; nt < 8; nt++)
#pragma unroll
            for (int c = 0; c < 4; c++) acc[mt][nt][c] = 0.f;

    uint32_t a_ld[2], b_ld[4];
#pragma unroll
    for (int mt = 0; mt < 2; mt++) {
        int row = wm * 32 + mt * 16 + ((lane >> 3) & 1) * 8 + (lane & 7);
        a_ld[mt] = (uint32_t)(row * 128 + (lane >> 4) * 16);
    }
#pragma unroll
    for (int p = 0; p < 4; p++) {
        int row = wn * 64 + p * 16 + (lane >> 4) * 8 + (lane & 7);
        b_ld[p] = (uint32_t)(row * 128 + ((lane >> 3) & 1) * 16);
    }

    // prologue: iter 0 into buffer 0
#pragma unroll
    for (int l = 0; l < 4; l++) {
        int row = r0 + l * 32;
        cp_async16(sb + swoff[l],         Abp + (size_t)row * ldA + c16 * 8);
        cp_async16(sb + 32768 + swoff[l], Bbp + (size_t)row * ldB + c16 * 8);
    }
    CP_COMMIT();

#pragma unroll 1
    for (int it = 0; it < iters; ++it) {
        int buf = it & 1;
        if (it + 1 < iters) {
            int nx = it + 1;
            int kwithin = (nx & 15) * 64;
            int aoff = (mode == 2) ? ((nx >> 4) * 1024 + kwithin) : kwithin;
            int boff = kwithin;
            const __half* Ak = Abp + aoff;
            const __half* Bk = Bbp + boff;
            uint32_t abase = sb + (buf ^ 1) * 16384;
            uint32_t bbase = sb + 32768 + (buf ^ 1) * 16384;
#pragma unroll
            for (int l = 0; l < 4; l++) {
                int row = r0 + l * 32;
                cp_async16(abase + swoff[l], Ak + (size_t)row * ldA + c16 * 8);
                cp_async16(bbase + swoff[l], Bk + (size_t)row * ldB + c16 * 8);
            }
            CP_COMMIT();
            CP_WAIT(1);
        } else {
            CP_WAIT(0);
        }
        __syncthreads();

        uint32_t ab = sb + buf * 16384;
        uint32_t bbS = sb + 32768 + buf * 16384;
#pragma unroll
        for (int s = 0; s < 4; ++s) {
            uint32_t kb = s * 32;
            uint32_t afr[2][4];
#pragma unroll
            for (int mt = 0; mt < 2; mt++) {
                uint32_t off = a_ld[mt] + kb;
                ldsm_x4(afr[mt], ab + (off ^ ((off >> 3) & 0x70)));
            }
            uint32_t bfr[8][2];
#pragma unroll
            for (int p = 0; p < 4; p++) {
                uint32_t off = b_ld[p] + kb;
                uint32_t r[4];
                ldsm_x4(r, bbS + (off ^ ((off >> 3) & 0x70)));
                bfr[2 * p][0] = r[0]; bfr[2 * p][1] = r[1];
                bfr[2 * p + 1][0] = r[2]; bfr[2 * p + 1][1] = r[3];
            }
#pragma unroll
            for (int mt = 0; mt < 2; mt++)
#pragma unroll
                for (int nt = 0; nt < 8; nt++)
                    mma16816(acc[mt][nt], afr[mt], bfr[nt]);
        }
        __syncthreads();
    }

    // epilogue: bias pointer by 1024-col segment (QKV: bx>>3 in {0,1,2})
    int bsel = bx >> 3;
    const float* bp = (bsel == 0) ? bias0 : (bsel == 1 ? bias1 : bias2);
    int bcol0 = (bx & 7) * 128;

    int g = lane >> 2, t4 = lane & 3;
#pragma unroll
    for (int mt = 0; mt < 2; mt++) {
        int row = by * 128 + wm * 32 + mt * 16 + g;
#pragma unroll
        for (int nt = 0; nt < 8; nt++) {
            int coff = wn * 64 + nt * 8 + t4 * 2;
            int col = bx * 128 + coff;
            float b0 = bp[bcol0 + coff], b1 = bp[bcol0 + coff + 1];
            float v0 = acc[mt][nt][0] + b0;
            float v1 = acc[mt][nt][1] + b1;
            float v2 = acc[mt][nt][2] + b0;
            float v3 = acc[mt][nt][3] + b1;
            if (relu) {
                v0 = fmaxf(v0, 0.f); v1 = fmaxf(v1, 0.f);
                v2 = fmaxf(v2, 0.f); v3 = fmaxf(v3, 0.f);
            }
            *(float2*)(C + (size_t)row * ldC + col)       = make_float2(v0, v1);
            *(float2*)(C + (size_t)(row + 8) * ldC + col) = make_float2(v2, v3);
        }
    }
}

// ---------------- importance logits ------------------------------------------
__global__ __launch_bounds__(256) void imp_kernel(
    const float* __restrict__ Hm, const float* __restrict__ Ws2,
    float* __restrict__ imp)
{
    int row  = blockIdx.x * 8 + (threadIdx.x >> 5);
    int lane = threadIdx.x & 31;
    const float* hr = Hm + (size_t)row * 512;
    float s = 0.f;
#pragma unroll 4
    for (int j = lane; j < 512; j += 32) s += hr[j] * Ws2[j];
#pragma unroll
    for (int o = 16; o > 0; o >>= 1) s += __shfl_xor_sync(0xffffffffu, s, o);
    if (lane == 0) imp[row] = s;
}

// ---------------- per-batch top-16: one warp per batch -----------------------
__global__ __launch_bounds__(32) void topk_kernel(
    const float* __restrict__ imp, int* __restrict__ topk,
    unsigned char* __restrict__ sel)
{
    __shared__ float vals[Ss];
    int b = blockIdx.x, lane = threadIdx.x;
    for (int j = lane; j < Ss; j += 32) {
        vals[j] = imp[b * Ss + j];
        sel[b * Ss + j] = 0;
    }
    __syncwarp();
    for (int it = 0; it < Kk; it++) {
        float m = -INFINITY; int mi = 0;
        for (int j = lane; j < Ss; j += 32) {
            float v = vals[j];
            if (v > m) { m = v; mi = j; }
        }
#pragma unroll
        for (int o = 16; o > 0; o >>= 1) {
            float om = __shfl_xor_sync(0xffffffffu, m, o);
            int   oi = __shfl_xor_sync(0xffffffffu, mi, o);
            if (om > m) { m = om; mi = oi; }
        }
        mi = __shfl_sync(0xffffffffu, mi, 0);
        if (lane == 0) {
            topk[b * Kk + it] = mi;
            sel[b * Ss + mi] = 1;
        }
        vals[mi] = -INFINITY;
        __syncwarp();
    }
}

// ---------------- sparse rows: 8 queries/block, kv+q staged in smem ----------
__global__ __launch_bounds__(256) void attn_sparse(
    const float* __restrict__ qkv, const int* __restrict__ topk,
    const unsigned char* __restrict__ sel, __half* __restrict__ aatt)
{
    __shared__ float k16[16 * 68];
    __shared__ float v16[16 * 68];
    __shared__ float qsm[8 * 64];

    int tid = threadIdx.x, w = tid >> 5, lane = tid & 31;
    int qid0 = blockIdx.x * 8;
    int b = qid0 >> 15;
    int rem = qid0 & 32767;
    int h = rem >> 11;
    int i0 = rem & 2047;
    int i = i0 + w;

    {
        int key = tid >> 4;
        int d0  = (tid & 15) * 4;
        int kj = topk[b * Kk + key];
        const float* kr = qkv + (size_t)(b * Ss + kj) * QKVN + 1024 + h * Dh + d0;
        const float* vr = kr + 1024;
        float4 kv = *(const float4*)kr;
        k16[key * 68 + d0 + 0] = kv.x; k16[key * 68 + d0 + 1] = kv.y;
        k16[key * 68 + d0 + 2] = kv.z; k16[key * 68 + d0 + 3] = kv.w;
        float4 vv = *(const float4*)vr;
        v16[key * 68 + d0 + 0] = vv.x; v16[key * 68 + d0 + 1] = vv.y;
        v16[key * 68 + d0 + 2] = vv.z; v16[key * 68 + d0 + 3] = vv.w;
    }
    {
        const float* qr = qkv + (size_t)(b * Ss + i) * QKVN + h * Dh;
        qsm[w * 64 + lane]      = qr[lane];
        qsm[w * 64 + lane + 32] = qr[lane + 32];
    }
    __syncthreads();

    if (sel[b * Ss + i]) return;

    float score = -INFINITY;
    if (lane < 16) {
        float s = 0.f;
#pragma unroll
        for (int d = 0; d < 64; d++) s += qsm[w * 64 + d] * k16[lane * 68 + d];
        score = s * 0.125f;
    }
    float m = score;
#pragma unroll
    for (int o = 16; o > 0; o >>= 1) m = fmaxf(m, __shfl_xor_sync(0xffffffffu, m, o));
    float e = (lane < 16) ? expf(score - m) : 0.f;
    float ssum = e;
#pragma unroll
    for (int o = 16; o > 0; o >>= 1) ssum += __shfl_xor_sync(0xffffffffu, ssum, o);
    float wgt = e / ssum;

    float acc0 = 0.f, acc1 = 0.f;
#pragma unroll
    for (int j = 0; j < 16; j++) {
        float wj = __shfl_sync(0xffffffffu, wgt, j);
        acc0 = fmaf(wj, v16[j * 68 + lane],      acc0);
        acc1 = fmaf(wj, v16[j * 68 + lane + 32], acc1);
    }
    size_t base = (size_t)(b * Ss + i) * 1024 + h * Dh;
    aatt[base + lane]      = __float2half(acc0);
    aatt[base + lane + 32] = __float2half(acc1);
}

// ---------------- dense rows: flash-style, one block per (b,h) ---------------
#define AD_QS   0
#define AD_KS   4096
#define AD_VS   (4096 + 33792)
#define AD_WS   (4096 + 33792 + 32768)
#define AD_SMEM (4096 + 33792 + 32768 + 8192)

__global__ __launch_bounds__(512) void attn_dense(
    const float* __restrict__ qkv, const int* __restrict__ topk,
    __half* __restrict__ aatt)
{
    extern __shared__ __align__(16) char smraw[];
    float* qs = (float*)(smraw + AD_QS);
    float* ks = (float*)(smraw + AD_KS);
    float* vs = (float*)(smraw + AD_VS);
    float* ws = (float*)(smraw + AD_WS);

    int tid = threadIdx.x, w = tid >> 5, lane = tid & 31;
    int b = blockIdx.x >> 4, h = blockIdx.x & 15;
    int i = topk[b * Kk + w];

    {
        const float* qr = qkv + (size_t)(b * Ss + i) * QKVN + h * Dh;
        qs[w * 64 + lane]      = qr[lane];
        qs[w * 64 + lane + 32] = qr[lane + 32];
    }

    float m_run = -INFINITY, sum_l = 0.f, acc0 = 0.f, acc1 = 0.f;

#pragma unroll 1
    for (int t = 0; t < 16; ++t) {
        __syncthreads();
        {
            int key = tid >> 2;
            int d0  = (tid & 3) * 16;
            const float* kr = qkv + (size_t)(b * Ss + t * 128 + key) * QKVN + 1024 + h * Dh + d0;
            const float* vr = kr + 1024;
#pragma unroll
            for (int u = 0; u < 4; u++) {
                float4 kv = *(const float4*)(kr + u * 4);
                int d = d0 + u * 4;
                ks[(d + 0) * 132 + key] = kv.x;
                ks[(d + 1) * 132 + key] = kv.y;
                ks[(d + 2) * 132 + key] = kv.z;
                ks[(d + 3) * 132 + key] = kv.w;
                *(float4*)(vs + key * 64 + d) = *(const float4*)(vr + u * 4);
            }
        }
        __syncthreads();

        float sc4[4];
        float mloc = -INFINITY;
#pragma unroll
        for (int c = 0; c < 4; c++) {
            int kk = lane + c * 32;
            float s = 0.f;
#pragma unroll
            for (int d = 0; d < 64; d++) s += qs[w * 64 + d] * ks[d * 132 + kk];
            s *= 0.125f;
            sc4[c] = s;
            mloc = fmaxf(mloc, s);
        }
#pragma unroll
        for (int o = 16; o > 0; o >>= 1)
            mloc = fmaxf(mloc, __shfl_xor_sync(0xffffffffu, mloc, o));
        float m_new = fmaxf(m_run, mloc);
        float scale = expf(m_run - m_new);
        acc0 *= scale; acc1 *= scale; sum_l *= scale;
#pragma unroll
        for (int c = 0; c < 4; c++) {
            float wv = expf(sc4[c] - m_new);
            ws[w * 128 + lane + c * 32] = wv;
            sum_l += wv;
        }
        m_run = m_new;
        __syncwarp();
#pragma unroll 4
        for (int j = 0; j < 128; j++) {
            float wj = ws[w * 128 + j];
            acc0 = fmaf(wj, vs[j * 64 + lane],      acc0);
            acc1 = fmaf(wj, vs[j * 64 + lane + 32], acc1);
        }
    }

    float sum = sum_l;
#pragma unroll
    for (int o = 16; o > 0; o >>= 1) sum += __shfl_xor_sync(0xffffffffu, sum, o);
    float inv = 1.f / sum;

    size_t base = (size_t)(b * Ss + i) * 1024 + h * Dh;
    aatt[base + lane]      = __float2half(acc0 * inv);
    aatt[base + lane + 32] = __float2half(acc1 * inv);
}

// ---------------- launcher ---------------------------------------------------
extern "C" void kernel_launch(void* const* d_in, const int* in_sizes, int n_in,
                              void* d_out, int out_size)
{
    const float* x   = (const float*)d_in[0];
    const float* Wq  = (const float*)d_in[1];
    const float* bq  = (const float*)d_in[2];
    const float* Wk  = (const float*)d_in[3];
    const float* bk  = (const float*)d_in[4];
    const float* Wv  = (const float*)d_in[5];
    const float* bv  = (const float*)d_in[6];
    const float* Wo  = (const float*)d_in[7];
    const float* bo  = (const float*)d_in[8];
    const float* Ws1 = (const float*)d_in[9];
    const float* bs1 = (const float*)d_in[10];
    const float* Ws2 = (const float*)d_in[11];
    float* out = (float*)d_out;

    float *qkv, *hbuf, *impb;
    int *tkb; unsigned char *selb;
    __half *a2x, *aatt, *bqkv, *boh, *bs1h;
    cudaGetSymbolAddress((void**)&qkv,  g_qkv);
    cudaGetSymbolAddress((void**)&hbuf, g_h);
    cudaGetSymbolAddress((void**)&impb, g_imp);
    cudaGetSymbolAddress((void**)&tkb,  g_topk);
    cudaGetSymbolAddress((void**)&selb, g_sel);
    cudaGetSymbolAddress((void**)&a2x,  g_a2x);
    cudaGetSymbolAddress((void**)&aatt, g_aatt);
    cudaGetSymbolAddress((void**)&bqkv, g_bqkv);
    cudaGetSymbolAddress((void**)&boh,  g_boh);
    cudaGetSymbolAddress((void**)&bs1h, g_bs1h);

    cudaFuncSetAttribute(gemm_tc, cudaFuncAttributeMaxDynamicSharedMemorySize,
                         GT_SMEM_TOTAL);
    cudaFuncSetAttribute(attn_dense, cudaFuncAttributeMaxDynamicSharedMemorySize,
                         AD_SMEM);

    // conversions (3 launches)
    splitA2_kernel<<<(Mrows * Dd) / 256, 256>>>(x, a2x);
    splitWh4_kernel<<<dim3(32, 32, 4), 256>>>(Wq, Wk, Wv, Wo, bqkv, boh);
    splitWh_kernel<<<dim3(16, 32), 256>>>(Ws1, bs1h, Dd / 2);

    // QKV hi-only GEMM: [4096,1024]x[3072,1024] -> qkv [4096,3072]
    gemm_tc<<<dim3(QKVN / 128, Mrows / 128), 256, GT_SMEM_TOTAL>>>(
        a2x, bqkv, bq, bk, bv, qkv, 2048, 1024, QKVN, 16, 0, 0);
    // S1 GEMM (2-chunk, relu): -> hbuf [4096,512]
    gemm_tc<<<dim3((Dd / 2) / 128, Mrows / 128), 256, GT_SMEM_TOTAL>>>(
        a2x, bs1h, bs1, bs1, bs1, hbuf, 2048, 1024, Dd / 2, 32, 2, 1);

    // indexer + top-k + attention
    imp_kernel<<<Mrows / 8, 256>>>(hbuf, Ws2, impb);
    topk_kernel<<<Bb, 32>>>(impb, tkb, selb);
    attn_sparse<<<(Bb * Hh * Ss) / 8, 256>>>(qkv, tkb, selb, aatt);
    attn_dense<<<Bb * Hh, 512, AD_SMEM>>>(qkv, tkb, aatt);

    // output projection (hi x hi)
    gemm_tc<<<dim3(Dd / 128, Mrows / 128), 256, GT_SMEM_TOTAL>>>(
        aatt, boh, bo, bo, bo, out, 1024, 1024, Dd, 16, 0, 0);
}

// round 10
// speedup vs baseline: 1.6558x; 1.0277x over previous
#include <cuda_runtime.h>
#include <cuda_fp16.h>
#include <math.h>
#include <stdint.h>

// Problem constants
#define Bb 2
#define Ss 2048
#define Dd 1024
#define Hh 16
#define Kk 16
#define Dh 64
#define Mrows (Bb * Ss)   // 4096
#define QKVN 3072         // concatenated q|k|v row width

// ---------------- scratch (device globals; no allocation allowed) ------------
__device__ float g_qkv[(size_t)Mrows * QKVN];   // q|k|v concatenated fp32
__device__ float g_h[Mrows * (Dd / 2)];
__device__ float g_imp[Mrows];
__device__ int   g_topk[Bb * Kk];
__device__ unsigned char g_sel[Bb * Ss];

// fp16 buffers
__device__ __half g_a2x[(size_t)Mrows * 2048];   // x:   [hi | lo]
__device__ __half g_aatt[(size_t)Mrows * 1024];  // att hi (written by attention)
__device__ __half g_bqkv[(size_t)QKVN * 1024];   // Wq^T|Wk^T|Wv^T hi
__device__ __half g_boh[(size_t)Dd * 1024];      // Wo^T hi
__device__ __half g_bs1h[(size_t)(Dd / 2) * 1024]; // Ws1^T hi

// ================= helpers ===================================================
__device__ __forceinline__ uint32_t smem_to_u32(const void* p) {
    uint32_t a;
    asm("{ .reg .u64 t; cvta.to.shared.u64 t, %1; cvt.u32.u64 %0, t; }" : "=r"(a) : "l"(p));
    return a;
}
__device__ __forceinline__ void cp_async16(uint32_t dst, const void* src) {
    asm volatile("cp.async.cg.shared.global [%0], [%1], 16;" :: "r"(dst), "l"(src));
}
#define CP_COMMIT() asm volatile("cp.async.commit_group;" ::: "memory")
#define CP_WAIT(n)  asm volatile("cp.async.wait_group %0;" :: "n"(n) : "memory")

__device__ __forceinline__ void ldsm_x4(uint32_t* r, uint32_t addr) {
    asm volatile("ldmatrix.sync.aligned.m8n8.x4.shared.b16 {%0,%1,%2,%3}, [%4];"
        : "=r"(r[0]), "=r"(r[1]), "=r"(r[2]), "=r"(r[3]) : "r"(addr));
}
__device__ __forceinline__ void mma16816(float* d, const uint32_t* a, const uint32_t* b) {
    asm volatile(
        "mma.sync.aligned.m16n8k16.row.col.f32.f16.f16.f32 "
        "{%0,%1,%2,%3}, {%4,%5,%6,%7}, {%8,%9}, {%0,%1,%2,%3};"
        : "+f"(d[0]), "+f"(d[1]), "+f"(d[2]), "+f"(d[3])
        : "r"(a[0]), "r"(a[1]), "r"(a[2]), "r"(a[3]), "r"(b[0]), "r"(b[1]));
}

// ================= conversion kernels ========================================
// fp32 [M,1024] -> fp16 [M, 2048] = [hi | lo]
__global__ __launch_bounds__(256) void splitA2_kernel(
    const float* __restrict__ A, __half* __restrict__ A2)
{
    int i = blockIdx.x * 256 + threadIdx.x;
    float a = A[i];
    __half hi = __float2half(a);
    __half lo = __float2half(a - __half2float(hi));
    int row = i >> 10, kcol = i & 1023;
    size_t base = (size_t)row * 2048;
    A2[base + kcol]        = hi;
    A2[base + 1024 + kcol] = lo;
}

// Batched weight transpose+quantize. z=0,1,2 -> bqkv; z=3 -> boh; z=4 -> bs1h.
__global__ __launch_bounds__(256) void splitWh5_kernel(
    const float* __restrict__ Wq, const float* __restrict__ Wk,
    const float* __restrict__ Wv, const float* __restrict__ Wo,
    const float* __restrict__ Ws1,
    __half* __restrict__ bqkv, __half* __restrict__ boh,
    __half* __restrict__ bs1h)
{
    __shared__ float tile[32][33];
    int z = blockIdx.z;
    int N = (z == 4) ? 512 : 1024;
    if (z == 4 && blockIdx.x >= 16) return;
    const float* W = (z == 0) ? Wq : (z == 1) ? Wk : (z == 2) ? Wv
                    : (z == 3) ? Wo : Ws1;
    __half* dst = (z < 3) ? (bqkv + (size_t)z * 1024 * 1024)
                : (z == 3) ? boh : bs1h;
    int tx = threadIdx.x & 31, ty = threadIdx.x >> 5;
    int n0 = blockIdx.x * 32, k0 = blockIdx.y * 32;
#pragma unroll
    for (int j = 0; j < 32; j += 8)
        tile[ty + j][tx] = W[(size_t)(k0 + ty + j) * N + n0 + tx];
    __syncthreads();
#pragma unroll
    for (int j = 0; j < 32; j += 8) {
        int n = ty + j;
        dst[(size_t)(n0 + n) * 1024 + k0 + tx] = __float2half(tile[tx][n]);
    }
}

// ================= tensor-core GEMM (mma.sync, fp16) =========================
// mode 0 (hi x hi):   aoff = boff = k
// mode 2 (2-chunk A): aoff = seg*1024 + k, boff = k   (exact A x B_hi)
// fusedS1: bx >= 24 CTAs run the S1 config (mode 2, 32 iters, relu, Cs1/ldC=512)
// CTA tile 128x128, BK=64, XOR swizzle, 256 threads, 3-stage cp.async pipeline.
// __launch_bounds__(256, 2): cap regs at 128 so 2 CTAs are resident per SM.
#define GT_SMEM_TOTAL 98304   // 3 stages x (16KB A + 16KB B)

__global__ __launch_bounds__(256, 2) void gemm_tc(
    const __half* __restrict__ A2, const __half* __restrict__ B2,
    const __half* __restrict__ Bs1,
    const float* __restrict__ bias0, const float* __restrict__ bias1,
    const float* __restrict__ bias2, const float* __restrict__ bias3,
    float* __restrict__ C, float* __restrict__ Cs1,
    int ldA, int ldC, int iters, int mode, int relu, int fusedS1)
{
    extern __shared__ __align__(1024) char smem[];
    uint32_t sb = smem_to_u32(smem);
    int tid = threadIdx.x, lane = tid & 31, wid = tid >> 5;
    int wm = wid & 3, wn = wid >> 2;
    int bx = blockIdx.x, by = blockIdx.y;

    // per-CTA config (uniform)
    int isS1 = (fusedS1 && bx >= 24);
    int bxl  = isS1 ? (bx - 24) : bx;
    const __half* Bsel = isS1 ? Bs1 : B2;
    float* Cc  = isS1 ? Cs1 : C;
    int ldCc   = isS1 ? 512 : ldC;
    int mm     = isS1 ? 2 : mode;
    int itrs   = isS1 ? 32 : iters;
    int rl     = isS1 ? 1 : relu;

    const __half* Abp = A2 + (size_t)by * 128 * ldA;
    const __half* Bbp = Bsel + (size_t)bxl * 128 * 1024;

    int r0  = tid >> 3;           // 0..31
    int c16 = tid & 7;            // 0..7
    uint32_t swoff[4];
#pragma unroll
    for (int l = 0; l < 4; l++) {
        uint32_t off = (r0 + l * 32) * 128 + c16 * 16;
        swoff[l] = off ^ ((off >> 3) & 0x70);
    }

    float acc[2][8][4];
#pragma unroll
    for (int mt = 0; mt < 2; mt++)
#pragma unroll
        for (int nt = 0; nt < 8; nt++)
#pragma unroll
            for (int c = 0; c < 4; c++) acc[mt][nt][c] = 0.f;

    uint32_t a_ld[2], b_ld[4];
#pragma unroll
    for (int mt = 0; mt < 2; mt++) {
        int row = wm * 32 + mt * 16 + ((lane >> 3) & 1) * 8 + (lane & 7);
        a_ld[mt] = (uint32_t)(row * 128 + (lane >> 4) * 16);
    }
#pragma unroll
    for (int p = 0; p < 4; p++) {
        int row = wn * 64 + p * 16 + (lane >> 4) * 8 + (lane & 7);
        b_ld[p] = (uint32_t)(row * 128 + ((lane >> 3) & 1) * 16);
    }

    // prologue: load iters 0,1 into stages 0,1
#pragma unroll 1
    for (int pre = 0; pre < 2; pre++) {
        int kw = (pre & 15) * 64;
        int aoff = (mm == 2) ? ((pre >> 4) * 1024 + kw) : kw;
        const __half* Ak = Abp + aoff;
        const __half* Bk = Bbp + kw;
        uint32_t abase = sb + pre * 16384;
        uint32_t bbase = sb + 49152 + pre * 16384;
#pragma unroll
        for (int l = 0; l < 4; l++) {
            int row = r0 + l * 32;
            cp_async16(abase + swoff[l], Ak + (size_t)row * ldA + c16 * 8);
            cp_async16(bbase + swoff[l], Bk + (size_t)row * 1024 + c16 * 8);
        }
        CP_COMMIT();
    }

#pragma unroll 1
    for (int it = 0; it < itrs; ++it) {
        if (it + 2 < itrs) {
            int nx = it + 2;
            int kw = (nx & 15) * 64;
            int aoff = (mm == 2) ? ((nx >> 4) * 1024 + kw) : kw;
            const __half* Ak = Abp + aoff;
            const __half* Bk = Bbp + kw;
            int st = nx % 3;
            uint32_t abase = sb + st * 16384;
            uint32_t bbase = sb + 49152 + st * 16384;
#pragma unroll
            for (int l = 0; l < 4; l++) {
                int row = r0 + l * 32;
                cp_async16(abase + swoff[l], Ak + (size_t)row * ldA + c16 * 8);
                cp_async16(bbase + swoff[l], Bk + (size_t)row * 1024 + c16 * 8);
            }
            CP_COMMIT();
            CP_WAIT(2);
        } else if (it + 1 < itrs) {
            CP_WAIT(1);
        } else {
            CP_WAIT(0);
        }
        __syncthreads();

        int st = it % 3;
        uint32_t ab  = sb + st * 16384;
        uint32_t bbS = sb + 49152 + st * 16384;
#pragma unroll
        for (int s = 0; s < 4; ++s) {
            uint32_t kb = s * 32;
            uint32_t afr[2][4];
#pragma unroll
            for (int mt = 0; mt < 2; mt++) {
                uint32_t off = a_ld[mt] + kb;
                ldsm_x4(afr[mt], ab + (off ^ ((off >> 3) & 0x70)));
            }
            uint32_t bfr[8][2];
#pragma unroll
            for (int p = 0; p < 4; p++) {
                uint32_t off = b_ld[p] + kb;
                uint32_t r[4];
                ldsm_x4(r, bbS + (off ^ ((off >> 3) & 0x70)));
                bfr[2 * p][0] = r[0]; bfr[2 * p][1] = r[1];
                bfr[2 * p + 1][0] = r[2]; bfr[2 * p + 1][1] = r[3];
            }
#pragma unroll
            for (int mt = 0; mt < 2; mt++)
#pragma unroll
                for (int nt = 0; nt < 8; nt++)
                    mma16816(acc[mt][nt], afr[mt], bfr[nt]);
        }
        __syncthreads();
    }

    // epilogue: bias selection
    const float* bp;
    int bcol0;
    if (isS1) { bp = bias3; bcol0 = bxl * 128; }
    else {
        int bsel = bx >> 3;
        bp = (bsel == 0) ? bias0 : (bsel == 1 ? bias1 : bias2);
        bcol0 = (bx & 7) * 128;
    }

    int g = lane >> 2, t4 = lane & 3;
#pragma unroll
    for (int mt = 0; mt < 2; mt++) {
        int row = by * 128 + wm * 32 + mt * 16 + g;
#pragma unroll
        for (int nt = 0; nt < 8; nt++) {
            int coff = wn * 64 + nt * 8 + t4 * 2;
            int col = bxl * 128 + coff;
            float b0 = bp[bcol0 + coff], b1 = bp[bcol0 + coff + 1];
            float v0 = acc[mt][nt][0] + b0;
            float v1 = acc[mt][nt][1] + b1;
            float v2 = acc[mt][nt][2] + b0;
            float v3 = acc[mt][nt][3] + b1;
            if (rl) {
                v0 = fmaxf(v0, 0.f); v1 = fmaxf(v1, 0.f);
                v2 = fmaxf(v2, 0.f); v3 = fmaxf(v3, 0.f);
            }
            *(float2*)(Cc + (size_t)row * ldCc + col)       = make_float2(v0, v1);
            *(float2*)(Cc + (size_t)(row + 8) * ldCc + col) = make_float2(v2, v3);
        }
    }
}

// ---------------- importance logits ------------------------------------------
__global__ __launch_bounds__(256) void imp_kernel(
    const float* __restrict__ Hm, const float* __restrict__ Ws2,
    float* __restrict__ imp)
{
    int row  = blockIdx.x * 8 + (threadIdx.x >> 5);
    int lane = threadIdx.x & 31;
    const float* hr = Hm + (size_t)row * 512;
    float s = 0.f;
#pragma unroll 4
    for (int j = lane; j < 512; j += 32) s += hr[j] * Ws2[j];
#pragma unroll
    for (int o = 16; o > 0; o >>= 1) s += __shfl_xor_sync(0xffffffffu, s, o);
    if (lane == 0) imp[row] = s;
}

// ---------------- per-batch top-16: one warp per batch -----------------------
__global__ __launch_bounds__(32) void topk_kernel(
    const float* __restrict__ imp, int* __restrict__ topk,
    unsigned char* __restrict__ sel)
{
    __shared__ float vals[Ss];
    int b = blockIdx.x, lane = threadIdx.x;
    for (int j = lane; j < Ss; j += 32) {
        vals[j] = imp[b * Ss + j];
        sel[b * Ss + j] = 0;
    }
    __syncwarp();
    for (int it = 0; it < Kk; it++) {
        float m = -INFINITY; int mi = 0;
        for (int j = lane; j < Ss; j += 32) {
            float v = vals[j];
            if (v > m) { m = v; mi = j; }
        }
#pragma unroll
        for (int o = 16; o > 0; o >>= 1) {
            float om = __shfl_xor_sync(0xffffffffu, m, o);
            int   oi = __shfl_xor_sync(0xffffffffu, mi, o);
            if (om > m) { m = om; mi = oi; }
        }
        mi = __shfl_sync(0xffffffffu, mi, 0);
        if (lane == 0) {
            topk[b * Kk + it] = mi;
            sel[b * Ss + mi] = 1;
        }
        vals[mi] = -INFINITY;
        __syncwarp();
    }
}

// ---------------- sparse rows: 8 queries/block, kv+q staged in smem ----------
__global__ __launch_bounds__(256) void attn_sparse(
    const float* __restrict__ qkv, const int* __restrict__ topk,
    const unsigned char* __restrict__ sel, __half* __restrict__ aatt)
{
    __shared__ float k16[16 * 68];
    __shared__ float v16[16 * 68];
    __shared__ float qsm[8 * 64];

    int tid = threadIdx.x, w = tid >> 5, lane = tid & 31;
    int qid0 = blockIdx.x * 8;
    int b = qid0 >> 15;
    int rem = qid0 & 32767;
    int h = rem >> 11;
    int i0 = rem & 2047;
    int i = i0 + w;

    {
        int key = tid >> 4;
        int d0  = (tid & 15) * 4;
        int kj = topk[b * Kk + key];
        const float* kr = qkv + (size_t)(b * Ss + kj) * QKVN + 1024 + h * Dh + d0;
        const float* vr = kr + 1024;
        float4 kv = *(const float4*)kr;
        k16[key * 68 + d0 + 0] = kv.x; k16[key * 68 + d0 + 1] = kv.y;
        k16[key * 68 + d0 + 2] = kv.z; k16[key * 68 + d0 + 3] = kv.w;
        float4 vv = *(const float4*)vr;
        v16[key * 68 + d0 + 0] = vv.x; v16[key * 68 + d0 + 1] = vv.y;
        v16[key * 68 + d0 + 2] = vv.z; v16[key * 68 + d0 + 3] = vv.w;
    }
    {
        const float* qr = qkv + (size_t)(b * Ss + i) * QKVN + h * Dh;
        qsm[w * 64 + lane]      = qr[lane];
        qsm[w * 64 + lane + 32] = qr[lane + 32];
    }
    __syncthreads();

    if (sel[b * Ss + i]) return;

    float score = -INFINITY;
    if (lane < 16) {
        float s = 0.f;
#pragma unroll
        for (int d = 0; d < 64; d++) s += qsm[w * 64 + d] * k16[lane * 68 + d];
        score = s * 0.125f;
    }
    float m = score;
#pragma unroll
    for (int o = 16; o > 0; o >>= 1) m = fmaxf(m, __shfl_xor_sync(0xffffffffu, m, o));
    float e = (lane < 16) ? expf(score - m) : 0.f;
    float ssum = e;
#pragma unroll
    for (int o = 16; o > 0; o >>= 1) ssum += __shfl_xor_sync(0xffffffffu, ssum, o);
    float wgt = e / ssum;

    float acc0 = 0.f, acc1 = 0.f;
#pragma unroll
    for (int j = 0; j < 16; j++) {
        float wj = __shfl_sync(0xffffffffu, wgt, j);
        acc0 = fmaf(wj, v16[j * 68 + lane],      acc0);
        acc1 = fmaf(wj, v16[j * 68 + lane + 32], acc1);
    }
    size_t base = (size_t)(b * Ss + i) * 1024 + h * Dh;
    aatt[base + lane]      = __float2half(acc0);
    aatt[base + lane + 32] = __float2half(acc1);
}

// ---------------- dense rows: flash-style, one block per (b,h) ---------------
#define AD_QS   0
#define AD_KS   4096
#define AD_VS   (4096 + 33792)
#define AD_WS   (4096 + 33792 + 32768)
#define AD_SMEM (4096 + 33792 + 32768 + 8192)

__global__ __launch_bounds__(512) void attn_dense(
    const float* __restrict__ qkv, const int* __restrict__ topk,
    __half* __restrict__ aatt)
{
    extern __shared__ __align__(16) char smraw[];
    float* qs = (float*)(smraw + AD_QS);
    float* ks = (float*)(smraw + AD_KS);
    float* vs = (float*)(smraw + AD_VS);
    float* ws = (float*)(smraw + AD_WS);

    int tid = threadIdx.x, w = tid >> 5, lane = tid & 31;
    int b = blockIdx.x >> 4, h = blockIdx.x & 15;
    int i = topk[b * Kk + w];

    {
        const float* qr = qkv + (size_t)(b * Ss + i) * QKVN + h * Dh;
        qs[w * 64 + lane]      = qr[lane];
        qs[w * 64 + lane + 32] = qr[lane + 32];
    }

    float m_run = -INFINITY, sum_l = 0.f, acc0 = 0.f, acc1 = 0.f;

#pragma unroll 1
    for (int t = 0; t < 16; ++t) {
        __syncthreads();
        {
            int key = tid >> 2;
            int d0  = (tid & 3) * 16;
            const float* kr = qkv + (size_t)(b * Ss + t * 128 + key) * QKVN + 1024 + h * Dh + d0;
            const float* vr = kr + 1024;
#pragma unroll
            for (int u = 0; u < 4; u++) {
                float4 kv = *(const float4*)(kr + u * 4);
                int d = d0 + u * 4;
                ks[(d + 0) * 132 + key] = kv.x;
                ks[(d + 1) * 132 + key] = kv.y;
                ks[(d + 2) * 132 + key] = kv.z;
                ks[(d + 3) * 132 + key] = kv.w;
                *(float4*)(vs + key * 64 + d) = *(const float4*)(vr + u * 4);
            }
        }
        __syncthreads();

        float sc4[4];
        float mloc = -INFINITY;
#pragma unroll
        for (int c = 0; c < 4; c++) {
            int kk = lane + c * 32;
            float s = 0.f;
#pragma unroll
            for (int d = 0; d < 64; d++) s += qs[w * 64 + d] * ks[d * 132 + kk];
            s *= 0.125f;
            sc4[c] = s;
            mloc = fmaxf(mloc, s);
        }
#pragma unroll
        for (int o = 16; o > 0; o >>= 1)
            mloc = fmaxf(mloc, __shfl_xor_sync(0xffffffffu, mloc, o));
        float m_new = fmaxf(m_run, mloc);
        float scale = expf(m_run - m_new);
        acc0 *= scale; acc1 *= scale; sum_l *= scale;
#pragma unroll
        for (int c = 0; c < 4; c++) {
            float wv = expf(sc4[c] - m_new);
            ws[w * 128 + lane + c * 32] = wv;
            sum_l += wv;
        }
        m_run = m_new;
        __syncwarp();
#pragma unroll 4
        for (int j = 0; j < 128; j++) {
            float wj = ws[w * 128 + j];
            acc0 = fmaf(wj, vs[j * 64 + lane],      acc0);
            acc1 = fmaf(wj, vs[j * 64 + lane + 32], acc1);
        }
    }

    float sum = sum_l;
#pragma unroll
    for (int o = 16; o > 0; o >>= 1) sum += __shfl_xor_sync(0xffffffffu, sum, o);
    float inv = 1.f / sum;

    size_t base = (size_t)(b * Ss + i) * 1024 + h * Dh;
    aatt[base + lane]      = __float2half(acc0 * inv);
    aatt[base + lane + 32] = __float2half(acc1 * inv);
}

// ---------------- launcher ---------------------------------------------------
extern "C" void kernel_launch(void* const* d_in, const int* in_sizes, int n_in,
                              void* d_out, int out_size)
{
    const float* x   = (const float*)d_in[0];
    const float* Wq  = (const float*)d_in[1];
    const float* bq  = (const float*)d_in[2];
    const float* Wk  = (const float*)d_in[3];
    const float* bk  = (const float*)d_in[4];
    const float* Wv  = (const float*)d_in[5];
    const float* bv  = (const float*)d_in[6];
    const float* Wo  = (const float*)d_in[7];
    const float* bo  = (const float*)d_in[8];
    const float* Ws1 = (const float*)d_in[9];
    const float* bs1 = (const float*)d_in[10];
    const float* Ws2 = (const float*)d_in[11];
    float* out = (float*)d_out;

    float *qkv, *hbuf, *impb;
    int *tkb; unsigned char *selb;
    __half *a2x, *aatt, *bqkv, *boh, *bs1h;
    cudaGetSymbolAddress((void**)&qkv,  g_qkv);
    cudaGetSymbolAddress((void**)&hbuf, g_h);
    cudaGetSymbolAddress((void**)&impb, g_imp);
    cudaGetSymbolAddress((void**)&tkb,  g_topk);
    cudaGetSymbolAddress((void**)&selb, g_sel);
    cudaGetSymbolAddress((void**)&a2x,  g_a2x);
    cudaGetSymbolAddress((void**)&aatt, g_aatt);
    cudaGetSymbolAddress((void**)&bqkv, g_bqkv);
    cudaGetSymbolAddress((void**)&boh,  g_boh);
    cudaGetSymbolAddress((void**)&bs1h, g_bs1h);

    cudaFuncSetAttribute(gemm_tc, cudaFuncAttributeMaxDynamicSharedMemorySize,
                         GT_SMEM_TOTAL);
    cudaFuncSetAttribute(attn_dense, cudaFuncAttributeMaxDynamicSharedMemorySize,
                         AD_SMEM);

    // conversions (2 launches)
    splitA2_kernel<<<(Mrows * Dd) / 256, 256>>>(x, a2x);
    splitWh5_kernel<<<dim3(32, 32, 5), 256>>>(Wq, Wk, Wv, Wo, Ws1, bqkv, boh, bs1h);

    // fused QKV (bx<24, hi x hi, 16 iters) + S1 (bx>=24, 2-chunk, 32 iters, relu)
    gemm_tc<<<dim3(QKVN / 128 + 4, Mrows / 128), 256, GT_SMEM_TOTAL>>>(
        a2x, bqkv, bs1h, bq, bk, bv, bs1, qkv, hbuf,
        2048, QKVN, 16, 0, 0, 1);

    // indexer + top-k + attention
    imp_kernel<<<Mrows / 8, 256>>>(hbuf, Ws2, impb);
    topk_kernel<<<Bb, 32>>>(impb, tkb, selb);
    attn_sparse<<<(Bb * Hh * Ss) / 8, 256>>>(qkv, tkb, selb, aatt);
    attn_dense<<<Bb * Hh, 512, AD_SMEM>>>(qkv, tkb, aatt);

    // output projection (hi x hi)
    gemm_tc<<<dim3(Dd / 128, Mrows / 128), 256, GT_SMEM_TOTAL>>>(
        aatt, boh, nullptr, bo, bo, bo, nullptr, out, nullptr,
        1024, Dd, 16, 0, 0, 0);
}

// round 11
// speedup vs baseline: 1.8308x; 1.1057x over previous
#include <cuda_runtime.h>
#include <cuda_fp16.h>
#include <math.h>
#include <stdint.h>

// Problem constants
#define Bb 2
#define Ss 2048
#define Dd 1024
#define Hh 16
#define Kk 16
#define Dh 64
#define Mrows (Bb * Ss)   // 4096
#define QKVN 3072         // concatenated q|k|v row width

// ---------------- scratch (device globals; no allocation allowed) ------------
__device__ __half g_qkvh[(size_t)Mrows * QKVN]; // q|k|v concatenated fp16
__device__ float g_h[Mrows * (Dd / 2)];
__device__ float g_imp[Mrows];
__device__ int   g_topk[Bb * Kk];
__device__ unsigned char g_sel[Bb * Ss];

// fp16 buffers
__device__ __half g_a2x[(size_t)Mrows * 2048];   // x:   [hi | lo]
__device__ __half g_aatt[(size_t)Mrows * 1024];  // att hi (written by attention)
__device__ __half g_bqkv[(size_t)QKVN * 1024];   // Wq^T|Wk^T|Wv^T hi
__device__ __half g_boh[(size_t)Dd * 1024];      // Wo^T hi
__device__ __half g_bs1h[(size_t)(Dd / 2) * 1024]; // Ws1^T hi

// ================= helpers ===================================================
__device__ __forceinline__ uint32_t smem_to_u32(const void* p) {
    uint32_t a;
    asm("{ .reg .u64 t; cvta.to.shared.u64 t, %1; cvt.u32.u64 %0, t; }" : "=r"(a) : "l"(p));
    return a;
}
__device__ __forceinline__ void cp_async16(uint32_t dst, const void* src) {
    asm volatile("cp.async.cg.shared.global [%0], [%1], 16;" :: "r"(dst), "l"(src));
}
#define CP_COMMIT() asm volatile("cp.async.commit_group;" ::: "memory")
#define CP_WAIT(n)  asm volatile("cp.async.wait_group %0;" :: "n"(n) : "memory")

__device__ __forceinline__ void ldsm_x4(uint32_t* r, uint32_t addr) {
    asm volatile("ldmatrix.sync.aligned.m8n8.x4.shared.b16 {%0,%1,%2,%3}, [%4];"
        : "=r"(r[0]), "=r"(r[1]), "=r"(r[2]), "=r"(r[3]) : "r"(addr));
}
__device__ __forceinline__ void mma16816(float* d, const uint32_t* a, const uint32_t* b) {
    asm volatile(
        "mma.sync.aligned.m16n8k16.row.col.f32.f16.f16.f32 "
        "{%0,%1,%2,%3}, {%4,%5,%6,%7}, {%8,%9}, {%0,%1,%2,%3};"
        : "+f"(d[0]), "+f"(d[1]), "+f"(d[2]), "+f"(d[3])
        : "r"(a[0]), "r"(a[1]), "r"(a[2]), "r"(a[3]), "r"(b[0]), "r"(b[1]));
}

// ================= conversion kernels ========================================
// fp32 [M,1024] -> fp16 [M, 2048] = [hi | lo]
__global__ __launch_bounds__(256) void splitA2_kernel(
    const float* __restrict__ A, __half* __restrict__ A2)
{
    int i = blockIdx.x * 256 + threadIdx.x;
    float a = A[i];
    __half hi = __float2half(a);
    __half lo = __float2half(a - __half2float(hi));
    int row = i >> 10, kcol = i & 1023;
    size_t base = (size_t)row * 2048;
    A2[base + kcol]        = hi;
    A2[base + 1024 + kcol] = lo;
}

// Batched weight transpose+quantize. z=0,1,2 -> bqkv; z=3 -> boh; z=4 -> bs1h.
__global__ __launch_bounds__(256) void splitWh5_kernel(
    const float* __restrict__ Wq, const float* __restrict__ Wk,
    const float* __restrict__ Wv, const float* __restrict__ Wo,
    const float* __restrict__ Ws1,
    __half* __restrict__ bqkv, __half* __restrict__ boh,
    __half* __restrict__ bs1h)
{
    __shared__ float tile[32][33];
    int z = blockIdx.z;
    int N = (z == 4) ? 512 : 1024;
    if (z == 4 && blockIdx.x >= 16) return;
    const float* W = (z == 0) ? Wq : (z == 1) ? Wk : (z == 2) ? Wv
                    : (z == 3) ? Wo : Ws1;
    __half* dst = (z < 3) ? (bqkv + (size_t)z * 1024 * 1024)
                : (z == 3) ? boh : bs1h;
    int tx = threadIdx.x & 31, ty = threadIdx.x >> 5;
    int n0 = blockIdx.x * 32, k0 = blockIdx.y * 32;
#pragma unroll
    for (int j = 0; j < 32; j += 8)
        tile[ty + j][tx] = W[(size_t)(k0 + ty + j) * N + n0 + tx];
    __syncthreads();
#pragma unroll
    for (int j = 0; j < 32; j += 8) {
        int n = ty + j;
        dst[(size_t)(n0 + n) * 1024 + k0 + tx] = __float2half(tile[tx][n]);
    }
}

// ================= tensor-core GEMM (mma.sync, fp16) =========================
// mode 0 (hi x hi):   aoff = boff = k
// mode 2 (2-chunk A): aoff = seg*1024 + k, boff = k   (exact A x B_hi)
// fusedS1: bx >= 24 CTAs run the S1 config (mode 2, 32 iters, relu, hbuf fp32)
// halfC:   non-S1 output stored as fp16 into Ch
// 3-stage cp.async pipeline, ONE barrier per iteration.
#define GT_SMEM_TOTAL 98304   // 3 stages x (16KB A + 16KB B)

__global__ __launch_bounds__(256, 2) void gemm_tc(
    const __half* __restrict__ A2, const __half* __restrict__ B2,
    const __half* __restrict__ Bs1,
    const float* __restrict__ bias0, const float* __restrict__ bias1,
    const float* __restrict__ bias2, const float* __restrict__ bias3,
    float* __restrict__ C, __half* __restrict__ Ch, float* __restrict__ Cs1,
    int ldA, int ldC, int iters, int mode, int relu, int fusedS1, int halfC)
{
    extern __shared__ __align__(1024) char smem[];
    uint32_t sb = smem_to_u32(smem);
    int tid = threadIdx.x, lane = tid & 31, wid = tid >> 5;
    int wm = wid & 3, wn = wid >> 2;
    int bx = blockIdx.x, by = blockIdx.y;

    int isS1 = (fusedS1 && bx >= 24);
    int bxl  = isS1 ? (bx - 24) : bx;
    const __half* Bsel = isS1 ? Bs1 : B2;
    int mm     = isS1 ? 2 : mode;
    int itrs   = isS1 ? 32 : iters;

    const __half* Abp = A2 + (size_t)by * 128 * ldA;
    const __half* Bbp = Bsel + (size_t)bxl * 128 * 1024;

    int r0  = tid >> 3;           // 0..31
    int c16 = tid & 7;            // 0..7
    uint32_t swoff[4];
#pragma unroll
    for (int l = 0; l < 4; l++) {
        uint32_t off = (r0 + l * 32) * 128 + c16 * 16;
        swoff[l] = off ^ ((off >> 3) & 0x70);
    }

    float acc[2][8][4];
#pragma unroll
    for (int mt = 0; mt < 2; mt++)
#pragma unroll
        for (int nt = 0; nt < 8; nt++)
#pragma unroll
            for (int c = 0; c < 4; c++) acc[mt][nt][c] = 0.f;

    uint32_t a_ld[2], b_ld[4];
#pragma unroll
    for (int mt = 0; mt < 2; mt++) {
        int row = wm * 32 + mt * 16 + ((lane >> 3) & 1) * 8 + (lane & 7);
        a_ld[mt] = (uint32_t)(row * 128 + (lane >> 4) * 16);
    }
#pragma unroll
    for (int p = 0; p < 4; p++) {
        int row = wn * 64 + p * 16 + (lane >> 4) * 8 + (lane & 7);
        b_ld[p] = (uint32_t)(row * 128 + ((lane >> 3) & 1) * 16);
    }

    // prologue: load iters 0,1 into stages 0,1
#pragma unroll 1
    for (int pre = 0; pre < 2; pre++) {
        int kw = pre * 64;
        const __half* Ak = Abp + kw;     // pre<16 so seg 0 in both modes
        const __half* Bk = Bbp + kw;
        uint32_t abase = sb + pre * 16384;
        uint32_t bbase = sb + 49152 + pre * 16384;
#pragma unroll
        for (int l = 0; l < 4; l++) {
            int row = r0 + l * 32;
            cp_async16(abase + swoff[l], Ak + (size_t)row * ldA + c16 * 8);
            cp_async16(bbase + swoff[l], Bk + (size_t)row * 1024 + c16 * 8);
        }
        CP_COMMIT();
    }

#pragma unroll 1
    for (int it = 0; it < itrs; ++it) {
        if (it + 1 < itrs) { CP_WAIT(1); } else { CP_WAIT(0); }
        __syncthreads();   // publishes stage it%3; protects overwrite of (it+2)%3
        if (it + 2 < itrs) {
            int nx = it + 2;
            int kw = (nx & 15) * 64;
            int aoff = (mm == 2) ? ((nx >> 4) * 1024 + kw) : kw;
            const __half* Ak = Abp + aoff;
            const __half* Bk = Bbp + kw;
            int st = nx % 3;
            uint32_t abase = sb + st * 16384;
            uint32_t bbase = sb + 49152 + st * 16384;
#pragma unroll
            for (int l = 0; l < 4; l++) {
                int row = r0 + l * 32;
                cp_async16(abase + swoff[l], Ak + (size_t)row * ldA + c16 * 8);
                cp_async16(bbase + swoff[l], Bk + (size_t)row * 1024 + c16 * 8);
            }
            CP_COMMIT();
        }

        int st = it % 3;
        uint32_t ab  = sb + st * 16384;
        uint32_t bbS = sb + 49152 + st * 16384;
#pragma unroll
        for (int s = 0; s < 4; ++s) {
            uint32_t kb = s * 32;
            uint32_t afr[2][4];
#pragma unroll
            for (int mt = 0; mt < 2; mt++) {
                uint32_t off = a_ld[mt] + kb;
                ldsm_x4(afr[mt], ab + (off ^ ((off >> 3) & 0x70)));
            }
            uint32_t bfr[8][2];
#pragma unroll
            for (int p = 0; p < 4; p++) {
                uint32_t off = b_ld[p] + kb;
                uint32_t r[4];
                ldsm_x4(r, bbS + (off ^ ((off >> 3) & 0x70)));
                bfr[2 * p][0] = r[0]; bfr[2 * p][1] = r[1];
                bfr[2 * p + 1][0] = r[2]; bfr[2 * p + 1][1] = r[3];
            }
#pragma unroll
            for (int mt = 0; mt < 2; mt++)
#pragma unroll
                for (int nt = 0; nt < 8; nt++)
                    mma16816(acc[mt][nt], afr[mt], bfr[nt]);
        }
    }

    // epilogue
    const float* bp;
    int bcol0;
    if (isS1) { bp = bias3; bcol0 = bxl * 128; }
    else {
        int bsel = bx >> 3;
        bp = (bsel == 0) ? bias0 : (bsel == 1 ? bias1 : bias2);
        bcol0 = (bx & 7) * 128;
    }

    int g = lane >> 2, t4 = lane & 3;
#pragma unroll
    for (int mt = 0; mt < 2; mt++) {
        int row = by * 128 + wm * 32 + mt * 16 + g;
#pragma unroll
        for (int nt = 0; nt < 8; nt++) {
            int coff = wn * 64 + nt * 8 + t4 * 2;
            int col = bxl * 128 + coff;
            float b0 = bp[bcol0 + coff], b1 = bp[bcol0 + coff + 1];
            float v0 = acc[mt][nt][0] + b0;
            float v1 = acc[mt][nt][1] + b1;
            float v2 = acc[mt][nt][2] + b0;
            float v3 = acc[mt][nt][3] + b1;
            if (isS1) {
                v0 = fmaxf(v0, 0.f); v1 = fmaxf(v1, 0.f);
                v2 = fmaxf(v2, 0.f); v3 = fmaxf(v3, 0.f);
                *(float2*)(Cs1 + (size_t)row * 512 + col)       = make_float2(v0, v1);
                *(float2*)(Cs1 + (size_t)(row + 8) * 512 + col) = make_float2(v2, v3);
            } else if (halfC) {
                *(__half2*)(Ch + (size_t)row * ldC + col)       = __floats2half2_rn(v0, v1);
                *(__half2*)(Ch + (size_t)(row + 8) * ldC + col) = __floats2half2_rn(v2, v3);
            } else {
                *(float2*)(C + (size_t)row * ldC + col)       = make_float2(v0, v1);
                *(float2*)(C + (size_t)(row + 8) * ldC + col) = make_float2(v2, v3);
            }
        }
    }
}

// ---------------- importance logits ------------------------------------------
__global__ __launch_bounds__(256) void imp_kernel(
    const float* __restrict__ Hm, const float* __restrict__ Ws2,
    float* __restrict__ imp)
{
    int row  = blockIdx.x * 8 + (threadIdx.x >> 5);
    int lane = threadIdx.x & 31;
    const float* hr = Hm + (size_t)row * 512;
    float s = 0.f;
#pragma unroll 4
    for (int j = lane; j < 512; j += 32) s += hr[j] * Ws2[j];
#pragma unroll
    for (int o = 16; o > 0; o >>= 1) s += __shfl_xor_sync(0xffffffffu, s, o);
    if (lane == 0) imp[row] = s;
}

// ---------------- per-batch top-16: one warp per batch -----------------------
__global__ __launch_bounds__(32) void topk_kernel(
    const float* __restrict__ imp, int* __restrict__ topk,
    unsigned char* __restrict__ sel)
{
    __shared__ float vals[Ss];
    int b = blockIdx.x, lane = threadIdx.x;
    for (int j = lane; j < Ss; j += 32) {
        vals[j] = imp[b * Ss + j];
        sel[b * Ss + j] = 0;
    }
    __syncwarp();
    for (int it = 0; it < Kk; it++) {
        float m = -INFINITY; int mi = 0;
        for (int j = lane; j < Ss; j += 32) {
            float v = vals[j];
            if (v > m) { m = v; mi = j; }
        }
#pragma unroll
        for (int o = 16; o > 0; o >>= 1) {
            float om = __shfl_xor_sync(0xffffffffu, m, o);
            int   oi = __shfl_xor_sync(0xffffffffu, mi, o);
            if (om > m) { m = om; mi = oi; }
        }
        mi = __shfl_sync(0xffffffffu, mi, 0);
        if (lane == 0) {
            topk[b * Kk + it] = mi;
            sel[b * Ss + mi] = 1;
        }
        vals[mi] = -INFINITY;
        __syncwarp();
    }
}

// ---------------- merged attention: dense (bx<32) + sparse (bx>=32) ----------
// 512 threads. qkv is fp16; math fp32 in smem/regs; output fp16 hi into aatt.
#define AD_QS   0                          // 16*64 floats (4KB)
#define AD_KS   4096                       // 64 x 132 floats
#define AD_VS   (4096 + 33792)             // 128 x 64 floats
#define AD_WS   (4096 + 33792 + 32768)     // 16 x 128 floats
#define AD_SMEM (4096 + 33792 + 32768 + 8192)   // 78848

__global__ __launch_bounds__(512) void attn_merged(
    const __half* __restrict__ qkv, const int* __restrict__ topk,
    const unsigned char* __restrict__ sel, __half* __restrict__ aatt)
{
    extern __shared__ __align__(16) char smraw[];
    float* qs = (float*)(smraw + AD_QS);
    float* ks = (float*)(smraw + AD_KS);
    float* vs = (float*)(smraw + AD_VS);
    float* ws = (float*)(smraw + AD_WS);

    int tid = threadIdx.x, w = tid >> 5, lane = tid & 31;

    if (blockIdx.x >= 32) {
        // ---------- sparse path: 16 queries per block ----------
        int sbx = blockIdx.x - 32;
        int qid0 = sbx * 16;
        int b = qid0 >> 15;
        int h = (qid0 >> 11) & 15;
        int i0 = qid0 & 2047;
        int i = i0 + w;

        // stage 16 selected k/v rows (threads 0..255)
        if (tid < 256) {
            int key = tid >> 4;
            int d0  = (tid & 15) * 4;
            int kj = topk[b * Kk + key];
            const __half* kr = qkv + (size_t)(b * Ss + kj) * QKVN + 1024 + h * Dh + d0;
            const __half* vr = kr + 1024;
            __half2 k0 = *(const __half2*)kr, k1 = *(const __half2*)(kr + 2);
            __half2 v0 = *(const __half2*)vr, v1 = *(const __half2*)(vr + 2);
            float2 kf0 = __half22float2(k0), kf1 = __half22float2(k1);
            float2 vf0 = __half22float2(v0), vf1 = __half22float2(v1);
            ks[key * 68 + d0 + 0] = kf0.x; ks[key * 68 + d0 + 1] = kf0.y;
            ks[key * 68 + d0 + 2] = kf1.x; ks[key * 68 + d0 + 3] = kf1.y;
            vs[key * 68 + d0 + 0] = vf0.x; vs[key * 68 + d0 + 1] = vf0.y;
            vs[key * 68 + d0 + 2] = vf1.x; vs[key * 68 + d0 + 3] = vf1.y;
        }
        // stage q row for this warp
        {
            const __half* qr = qkv + (size_t)(b * Ss + i) * QKVN + h * Dh;
            qs[w * 64 + lane]      = __half2float(qr[lane]);
            qs[w * 64 + lane + 32] = __half2float(qr[lane + 32]);
        }
        __syncthreads();

        if (sel[b * Ss + i]) return;   // dense path handles selected rows

        float score = -INFINITY;
        if (lane < 16) {
            float s = 0.f;
#pragma unroll
            for (int d = 0; d < 64; d++) s += qs[w * 64 + d] * ks[lane * 68 + d];
            score = s * 0.125f;
        }
        float m = score;
#pragma unroll
        for (int o = 16; o > 0; o >>= 1) m = fmaxf(m, __shfl_xor_sync(0xffffffffu, m, o));
        float e = (lane < 16) ? expf(score - m) : 0.f;
        float ssum = e;
#pragma unroll
        for (int o = 16; o > 0; o >>= 1) ssum += __shfl_xor_sync(0xffffffffu, ssum, o);
        float wgt = e / ssum;

        float acc0 = 0.f, acc1 = 0.f;
#pragma unroll
        for (int j = 0; j < 16; j++) {
            float wj = __shfl_sync(0xffffffffu, wgt, j);
            acc0 = fmaf(wj, vs[j * 68 + lane],      acc0);
            acc1 = fmaf(wj, vs[j * 68 + lane + 32], acc1);
        }
        size_t base = (size_t)(b * Ss + i) * 1024 + h * Dh;
        aatt[base + lane]      = __float2half(acc0);
        aatt[base + lane + 32] = __float2half(acc1);
        return;
    }

    // ---------- dense path: one block per (b,h), 16 warps = 16 queries -------
    int b = blockIdx.x >> 4, h = blockIdx.x & 15;
    int i = topk[b * Kk + w];

    {
        const __half* qr = qkv + (size_t)(b * Ss + i) * QKVN + h * Dh;
        qs[w * 64 + lane]      = __half2float(qr[lane]);
        qs[w * 64 + lane + 32] = __half2float(qr[lane + 32]);
    }

    float m_run = -INFINITY, sum_l = 0.f, acc0 = 0.f, acc1 = 0.f;

#pragma unroll 1
    for (int t = 0; t < 16; ++t) {
        __syncthreads();
        {
            int key = tid >> 2;
            int d0  = (tid & 3) * 16;
            const __half* kr = qkv + (size_t)(b * Ss + t * 128 + key) * QKVN + 1024 + h * Dh + d0;
            const __half* vr = kr + 1024;
#pragma unroll
            for (int u = 0; u < 4; u++) {
                __half2 kp0 = *(const __half2*)(kr + u * 4);
                __half2 kp1 = *(const __half2*)(kr + u * 4 + 2);
                float2 kf0 = __half22float2(kp0), kf1 = __half22float2(kp1);
                int d = d0 + u * 4;
                ks[(d + 0) * 132 + key] = kf0.x;
                ks[(d + 1) * 132 + key] = kf0.y;
                ks[(d + 2) * 132 + key] = kf1.x;
                ks[(d + 3) * 132 + key] = kf1.y;
                __half2 vp0 = *(const __half2*)(vr + u * 4);
                __half2 vp1 = *(const __half2*)(vr + u * 4 + 2);
                float2 vf0 = __half22float2(vp0), vf1 = __half22float2(vp1);
                *(float4*)(vs + key * 64 + d) = make_float4(vf0.x, vf0.y, vf1.x, vf1.y);
            }
        }
        __syncthreads();

        float sc4[4];
        float mloc = -INFINITY;
#pragma unroll
        for (int c = 0; c < 4; c++) {
            int kk = lane + c * 32;
            float s = 0.f;
#pragma unroll
            for (int d = 0; d < 64; d++) s += qs[w * 64 + d] * ks[d * 132 + kk];
            s *= 0.125f;
            sc4[c] = s;
            mloc = fmaxf(mloc, s);
        }
#pragma unroll
        for (int o = 16; o > 0; o >>= 1)
            mloc = fmaxf(mloc, __shfl_xor_sync(0xffffffffu, mloc, o));
        float m_new = fmaxf(m_run, mloc);
        float scale = expf(m_run - m_new);
        acc0 *= scale; acc1 *= scale; sum_l *= scale;
#pragma unroll
        for (int c = 0; c < 4; c++) {
            float wv = expf(sc4[c] - m_new);
            ws[w * 128 + lane + c * 32] = wv;
            sum_l += wv;
        }
        m_run = m_new;
        __syncwarp();
#pragma unroll 4
        for (int j = 0; j < 128; j++) {
            float wj = ws[w * 128 + j];
            acc0 = fmaf(wj, vs[j * 64 + lane],      acc0);
            acc1 = fmaf(wj, vs[j * 64 + lane + 32], acc1);
        }
    }

    float sum = sum_l;
#pragma unroll
    for (int o = 16; o > 0; o >>= 1) sum += __shfl_xor_sync(0xffffffffu, sum, o);
    float inv = 1.f / sum;

    size_t base = (size_t)(b * Ss + i) * 1024 + h * Dh;
    aatt[base + lane]      = __float2half(acc0 * inv);
    aatt[base + lane + 32] = __float2half(acc1 * inv);
}

// ---------------- launcher ---------------------------------------------------
extern "C" void kernel_launch(void* const* d_in, const int* in_sizes, int n_in,
                              void* d_out, int out_size)
{
    const float* x   = (const float*)d_in[0];
    const float* Wq  = (const float*)d_in[1];
    const float* bq  = (const float*)d_in[2];
    const float* Wk  = (const float*)d_in[3];
    const float* bk  = (const float*)d_in[4];
    const float* Wv  = (const float*)d_in[5];
    const float* bv  = (const float*)d_in[6];
    const float* Wo  = (const float*)d_in[7];
    const float* bo  = (const float*)d_in[8];
    const float* Ws1 = (const float*)d_in[9];
    const float* bs1 = (const float*)d_in[10];
    const float* Ws2 = (const float*)d_in[11];
    float* out = (float*)d_out;

    float *hbuf, *impb;
    int *tkb; unsigned char *selb;
    __half *qkvh, *a2x, *aatt, *bqkv, *boh, *bs1h;
    cudaGetSymbolAddress((void**)&qkvh, g_qkvh);
    cudaGetSymbolAddress((void**)&hbuf, g_h);
    cudaGetSymbolAddress((void**)&impb, g_imp);
    cudaGetSymbolAddress((void**)&tkb,  g_topk);
    cudaGetSymbolAddress((void**)&selb, g_sel);
    cudaGetSymbolAddress((void**)&a2x,  g_a2x);
    cudaGetSymbolAddress((void**)&aatt, g_aatt);
    cudaGetSymbolAddress((void**)&bqkv, g_bqkv);
    cudaGetSymbolAddress((void**)&boh,  g_boh);
    cudaGetSymbolAddress((void**)&bs1h, g_bs1h);

    cudaFuncSetAttribute(gemm_tc, cudaFuncAttributeMaxDynamicSharedMemorySize,
                         GT_SMEM_TOTAL);
    cudaFuncSetAttribute(attn_merged, cudaFuncAttributeMaxDynamicSharedMemorySize,
                         AD_SMEM);

    // conversions
    splitA2_kernel<<<(Mrows * Dd) / 256, 256>>>(x, a2x);
    splitWh5_kernel<<<dim3(32, 32, 5), 256>>>(Wq, Wk, Wv, Wo, Ws1, bqkv, boh, bs1h);

    // fused QKV (bx<24, hi x hi -> fp16 qkv) + S1 (bx>=24, 2-chunk, relu -> fp32 hbuf)
    gemm_tc<<<dim3(QKVN / 128 + 4, Mrows / 128), 256, GT_SMEM_TOTAL>>>(
        a2x, bqkv, bs1h, bq, bk, bv, bs1, nullptr, qkvh, hbuf,
        2048, QKVN, 16, 0, 0, 1, 1);

    // indexer + top-k + attention (merged)
    imp_kernel<<<Mrows / 8, 256>>>(hbuf, Ws2, impb);
    topk_kernel<<<Bb, 32>>>(impb, tkb, selb);
    attn_merged<<<32 + (Bb * Hh * Ss) / 16, 512, AD_SMEM>>>(qkvh, tkb, selb, aatt);

    // output projection (hi x hi -> fp32 out)
    gemm_tc<<<dim3(Dd / 128, Mrows / 128), 256, GT_SMEM_TOTAL>>>(
        aatt, boh, nullptr, bo, bo, bo, nullptr, out, nullptr, nullptr,
        1024, Dd, 16, 0, 0, 0, 0);
}

// round 12
// speedup vs baseline: 1.8458x; 1.0082x over previous
#include <cuda_runtime.h>
#include <cuda_fp16.h>
#include <math.h>
#include <stdint.h>

// Problem constants
#define Bb 2
#define Ss 2048
#define Dd 1024
#define Hh 16
#define Kk 16
#define Dh 64
#define Mrows (Bb * Ss)   // 4096
#define QKVN 3072         // concatenated q|k|v row width

// ---------------- scratch (device globals; no allocation allowed) ------------
__device__ __half g_qkvh[(size_t)Mrows * QKVN]; // q|k|v concatenated fp16
__device__ float g_h[Mrows * (Dd / 2)];
__device__ float g_imp[Mrows];
__device__ int   g_topk[Bb * Kk];
__device__ unsigned char g_sel[Bb * Ss];

// fp16 buffers
__device__ __half g_a2x[(size_t)Mrows * 2048];   // x:   [hi | lo]
__device__ __half g_aatt[(size_t)Mrows * 1024];  // att hi (written by attention)
__device__ __half g_bqkv[(size_t)QKVN * 1024];   // Wq^T|Wk^T|Wv^T hi
__device__ __half g_boh[(size_t)Dd * 1024];      // Wo^T hi
__device__ __half g_bs1h[(size_t)(Dd / 2) * 1024]; // Ws1^T hi

// ================= helpers ===================================================
__device__ __forceinline__ uint32_t smem_to_u32(const void* p) {
    uint32_t a;
    asm("{ .reg .u64 t; cvta.to.shared.u64 t, %1; cvt.u32.u64 %0, t; }" : "=r"(a) : "l"(p));
    return a;
}
__device__ __forceinline__ void cp_async16(uint32_t dst, const void* src) {
    asm volatile("cp.async.cg.shared.global [%0], [%1], 16;" :: "r"(dst), "l"(src));
}
#define CP_COMMIT() asm volatile("cp.async.commit_group;" ::: "memory")
#define CP_WAIT(n)  asm volatile("cp.async.wait_group %0;" :: "n"(n) : "memory")

__device__ __forceinline__ void ldsm_x4(uint32_t* r, uint32_t addr) {
    asm volatile("ldmatrix.sync.aligned.m8n8.x4.shared.b16 {%0,%1,%2,%3}, [%4];"
        : "=r"(r[0]), "=r"(r[1]), "=r"(r[2]), "=r"(r[3]) : "r"(addr));
}
__device__ __forceinline__ void mma16816(float* d, const uint32_t* a, const uint32_t* b) {
    asm volatile(
        "mma.sync.aligned.m16n8k16.row.col.f32.f16.f16.f32 "
        "{%0,%1,%2,%3}, {%4,%5,%6,%7}, {%8,%9}, {%0,%1,%2,%3};"
        : "+f"(d[0]), "+f"(d[1]), "+f"(d[2]), "+f"(d[3])
        : "r"(a[0]), "r"(a[1]), "r"(a[2]), "r"(a[3]), "r"(b[0]), "r"(b[1]));
}

// ================= conversion kernels ========================================
// fp32 [M,1024] -> fp16 [M, 2048] = [hi | lo]
__global__ __launch_bounds__(256) void splitA2_kernel(
    const float* __restrict__ A, __half* __restrict__ A2)
{
    int i = blockIdx.x * 256 + threadIdx.x;
    float a = A[i];
    __half hi = __float2half(a);
    __half lo = __float2half(a - __half2float(hi));
    int row = i >> 10, kcol = i & 1023;
    size_t base = (size_t)row * 2048;
    A2[base + kcol]        = hi;
    A2[base + 1024 + kcol] = lo;
}

// Batched weight transpose+quantize. z=0,1,2 -> bqkv; z=3 -> boh; z=4 -> bs1h.
__global__ __launch_bounds__(256) void splitWh5_kernel(
    const float* __restrict__ Wq, const float* __restrict__ Wk,
    const float* __restrict__ Wv, const float* __restrict__ Wo,
    const float* __restrict__ Ws1,
    __half* __restrict__ bqkv, __half* __restrict__ boh,
    __half* __restrict__ bs1h)
{
    __shared__ float tile[32][33];
    int z = blockIdx.z;
    int N = (z == 4) ? 512 : 1024;
    if (z == 4 && blockIdx.x >= 16) return;
    const float* W = (z == 0) ? Wq : (z == 1) ? Wk : (z == 2) ? Wv
                    : (z == 3) ? Wo : Ws1;
    __half* dst = (z < 3) ? (bqkv + (size_t)z * 1024 * 1024)
                : (z == 3) ? boh : bs1h;
    int tx = threadIdx.x & 31, ty = threadIdx.x >> 5;
    int n0 = blockIdx.x * 32, k0 = blockIdx.y * 32;
#pragma unroll
    for (int j = 0; j < 32; j += 8)
        tile[ty + j][tx] = W[(size_t)(k0 + ty + j) * N + n0 + tx];
    __syncthreads();
#pragma unroll
    for (int j = 0; j < 32; j += 8) {
        int n = ty + j;
        dst[(size_t)(n0 + n) * 1024 + k0 + tx] = __float2half(tile[tx][n]);
    }
}

// ================= tensor-core GEMM (mma.sync, fp16) =========================
// mode 0 (hi x hi):   aoff = boff = k
// mode 2 (2-chunk A): aoff = seg*1024 + k, boff = k   (exact A x B_hi)
// fusedS1: bx < 4 CTAs run the S1 config (mode 2, 32 iters, relu, hbuf fp32);
//          S1 CTAs are the 2x-long poles, so they get the LOWEST block ids
//          (scheduled first) to avoid a straggler tail wave.
// halfC:   non-S1 output stored as fp16 into Ch
// 3-stage cp.async pipeline, ONE barrier per iteration.
#define GT_SMEM_TOTAL 98304   // 3 stages x (16KB A + 16KB B)

__global__ __launch_bounds__(256, 2) void gemm_tc(
    const __half* __restrict__ A2, const __half* __restrict__ B2,
    const __half* __restrict__ Bs1,
    const float* __restrict__ bias0, const float* __restrict__ bias1,
    const float* __restrict__ bias2, const float* __restrict__ bias3,
    float* __restrict__ C, __half* __restrict__ Ch, float* __restrict__ Cs1,
    int ldA, int ldC, int iters, int mode, int relu, int fusedS1, int halfC)
{
    extern __shared__ __align__(1024) char smem[];
    uint32_t sb = smem_to_u32(smem);
    int tid = threadIdx.x, lane = tid & 31, wid = tid >> 5;
    int wm = wid & 3, wn = wid >> 2;
    int bx = blockIdx.x, by = blockIdx.y;

    int isS1 = (fusedS1 && bx < 4);
    int bxl  = fusedS1 ? (isS1 ? bx : bx - 4) : bx;
    const __half* Bsel = isS1 ? Bs1 : B2;
    int mm     = isS1 ? 2 : mode;
    int itrs   = isS1 ? 32 : iters;

    const __half* Abp = A2 + (size_t)by * 128 * ldA;
    const __half* Bbp = Bsel + (size_t)bxl * 128 * 1024;

    int r0  = tid >> 3;           // 0..31
    int c16 = tid & 7;            // 0..7
    uint32_t swoff[4];
#pragma unroll
    for (int l = 0; l < 4; l++) {
        uint32_t off = (r0 + l * 32) * 128 + c16 * 16;
        swoff[l] = off ^ ((off >> 3) & 0x70);
    }

    float acc[2][8][4];
#pragma unroll
    for (int mt = 0; mt < 2; mt++)
#pragma unroll
        for (int nt = 0; nt < 8; nt++)
#pragma unroll
            for (int c = 0; c < 4; c++) acc[mt][nt][c] = 0.f;

    uint32_t a_ld[2], b_ld[4];
#pragma unroll
    for (int mt = 0; mt < 2; mt++) {
        int row = wm * 32 + mt * 16 + ((lane >> 3) & 1) * 8 + (lane & 7);
        a_ld[mt] = (uint32_t)(row * 128 + (lane >> 4) * 16);
    }
#pragma unroll
    for (int p = 0; p < 4; p++) {
        int row = wn * 64 + p * 16 + (lane >> 4) * 8 + (lane & 7);
        b_ld[p] = (uint32_t)(row * 128 + ((lane >> 3) & 1) * 16);
    }

    // prologue: load iters 0,1 into stages 0,1 (always seg 0 in both modes)
#pragma unroll 1
    for (int pre = 0; pre < 2; pre++) {
        int kw = pre * 64;
        const __half* Ak = Abp + kw;
        const __half* Bk = Bbp + kw;
        uint32_t abase = sb + pre * 16384;
        uint32_t bbase = sb + 49152 + pre * 16384;
#pragma unroll
        for (int l = 0; l < 4; l++) {
            int row = r0 + l * 32;
            cp_async16(abase + swoff[l], Ak + (size_t)row * ldA + c16 * 8);
            cp_async16(bbase + swoff[l], Bk + (size_t)row * 1024 + c16 * 8);
        }
        CP_COMMIT();
    }

#pragma unroll 1
    for (int it = 0; it < itrs; ++it) {
        if (it + 1 < itrs) { CP_WAIT(1); } else { CP_WAIT(0); }
        __syncthreads();   // publishes stage it%3; protects overwrite of (it+2)%3
        if (it + 2 < itrs) {
            int nx = it + 2;
            int kw = (nx & 15) * 64;
            int aoff = (mm == 2) ? ((nx >> 4) * 1024 + kw) : kw;
            const __half* Ak = Abp + aoff;
            const __half* Bk = Bbp + kw;
            int st = nx % 3;
            uint32_t abase = sb + st * 16384;
            uint32_t bbase = sb + 49152 + st * 16384;
#pragma unroll
            for (int l = 0; l < 4; l++) {
                int row = r0 + l * 32;
                cp_async16(abase + swoff[l], Ak + (size_t)row * ldA + c16 * 8);
                cp_async16(bbase + swoff[l], Bk + (size_t)row * 1024 + c16 * 8);
            }
            CP_COMMIT();
        }

        int st = it % 3;
        uint32_t ab  = sb + st * 16384;
        uint32_t bbS = sb + 49152 + st * 16384;
#pragma unroll
        for (int s = 0; s < 4; ++s) {
            uint32_t kb = s * 32;
            uint32_t afr[2][4];
#pragma unroll
            for (int mt = 0; mt < 2; mt++) {
                uint32_t off = a_ld[mt] + kb;
                ldsm_x4(afr[mt], ab + (off ^ ((off >> 3) & 0x70)));
            }
            uint32_t bfr[8][2];
#pragma unroll
            for (int p = 0; p < 4; p++) {
                uint32_t off = b_ld[p] + kb;
                uint32_t r[4];
                ldsm_x4(r, bbS + (off ^ ((off >> 3) & 0x70)));
                bfr[2 * p][0] = r[0]; bfr[2 * p][1] = r[1];
                bfr[2 * p + 1][0] = r[2]; bfr[2 * p + 1][1] = r[3];
            }
#pragma unroll
            for (int mt = 0; mt < 2; mt++)
#pragma unroll
                for (int nt = 0; nt < 8; nt++)
                    mma16816(acc[mt][nt], afr[mt], bfr[nt]);
        }
    }

    // epilogue
    const float* bp;
    int bcol0;
    if (isS1) { bp = bias3; bcol0 = bxl * 128; }
    else {
        int bsel = bxl >> 3;
        bp = (bsel == 0) ? bias0 : (bsel == 1 ? bias1 : bias2);
        bcol0 = (bxl & 7) * 128;
    }

    int g = lane >> 2, t4 = lane & 3;
#pragma unroll
    for (int mt = 0; mt < 2; mt++) {
        int row = by * 128 + wm * 32 + mt * 16 + g;
#pragma unroll
        for (int nt = 0; nt < 8; nt++) {
            int coff = wn * 64 + nt * 8 + t4 * 2;
            int col = bxl * 128 + coff;
            float b0 = bp[bcol0 + coff], b1 = bp[bcol0 + coff + 1];
            float v0 = acc[mt][nt][0] + b0;
            float v1 = acc[mt][nt][1] + b1;
            float v2 = acc[mt][nt][2] + b0;
            float v3 = acc[mt][nt][3] + b1;
            if (isS1) {
                v0 = fmaxf(v0, 0.f); v1 = fmaxf(v1, 0.f);
                v2 = fmaxf(v2, 0.f); v3 = fmaxf(v3, 0.f);
                *(float2*)(Cs1 + (size_t)row * 512 + col)       = make_float2(v0, v1);
                *(float2*)(Cs1 + (size_t)(row + 8) * 512 + col) = make_float2(v2, v3);
            } else if (halfC) {
                *(__half2*)(Ch + (size_t)row * ldC + col)       = __floats2half2_rn(v0, v1);
                *(__half2*)(Ch + (size_t)(row + 8) * ldC + col) = __floats2half2_rn(v2, v3);
            } else {
                *(float2*)(C + (size_t)row * ldC + col)       = make_float2(v0, v1);
                *(float2*)(C + (size_t)(row + 8) * ldC + col) = make_float2(v2, v3);
            }
        }
    }
}

// ---------------- importance logits (float4 loads, MLP 4) --------------------
__global__ __launch_bounds__(256) void imp_kernel(
    const float* __restrict__ Hm, const float* __restrict__ Ws2,
    float* __restrict__ imp)
{
    int row  = blockIdx.x * 8 + (threadIdx.x >> 5);
    int lane = threadIdx.x & 31;
    const float4* hr4 = (const float4*)(Hm + (size_t)row * 512);
    const float4* w4  = (const float4*)Ws2;
    float s = 0.f;
#pragma unroll
    for (int j = lane; j < 128; j += 32) {
        float4 a = hr4[j], b = w4[j];
        s += a.x * b.x + a.y * b.y + a.z * b.z + a.w * b.w;
    }
#pragma unroll
    for (int o = 16; o > 0; o >>= 1) s += __shfl_xor_sync(0xffffffffu, s, o);
    if (lane == 0) imp[row] = s;
}

// ---------------- per-batch top-16: one warp per batch -----------------------
__global__ __launch_bounds__(32) void topk_kernel(
    const float* __restrict__ imp, int* __restrict__ topk,
    unsigned char* __restrict__ sel)
{
    __shared__ float vals[Ss];
    int b = blockIdx.x, lane = threadIdx.x;
    for (int j = lane; j < Ss; j += 32) {
        vals[j] = imp[b * Ss + j];
        sel[b * Ss + j] = 0;
    }
    __syncwarp();
    for (int it = 0; it < Kk; it++) {
        float m = -INFINITY; int mi = 0;
        for (int j = lane; j < Ss; j += 32) {
            float v = vals[j];
            if (v > m) { m = v; mi = j; }
        }
#pragma unroll
        for (int o = 16; o > 0; o >>= 1) {
            float om = __shfl_xor_sync(0xffffffffu, m, o);
            int   oi = __shfl_xor_sync(0xffffffffu, mi, o);
            if (om > m) { m = om; mi = oi; }
        }
        mi = __shfl_sync(0xffffffffu, mi, 0);
        if (lane == 0) {
            topk[b * Kk + it] = mi;
            sel[b * Ss + mi] = 1;
        }
        vals[mi] = -INFINITY;
        __syncwarp();
    }
}

// ---------------- merged attention: dense (bx<32) + sparse (bx>=32) ----------
// 512 threads. Sparse blocks handle 32 queries (2 rounds of 16) sharing one
// staged K/V16. qkv fp16; math fp32; output fp16 hi into aatt.
#define AD_QS   0                          // 16*64 floats (4KB)
#define AD_KS   4096                       // 64 x 132 floats
#define AD_VS   (4096 + 33792)             // 128 x 64 floats
#define AD_WS   (4096 + 33792 + 32768)     // 16 x 128 floats
#define AD_SMEM (4096 + 33792 + 32768 + 8192)   // 78848

__global__ __launch_bounds__(512) void attn_merged(
    const __half* __restrict__ qkv, const int* __restrict__ topk,
    const unsigned char* __restrict__ sel, __half* __restrict__ aatt)
{
    extern __shared__ __align__(16) char smraw[];
    float* qs = (float*)(smraw + AD_QS);
    float* ks = (float*)(smraw + AD_KS);
    float* vs = (float*)(smraw + AD_VS);
    float* ws = (float*)(smraw + AD_WS);

    int tid = threadIdx.x, w = tid >> 5, lane = tid & 31;

    if (blockIdx.x >= 32) {
        // ---------- sparse path: 32 queries per block, 2 rounds ----------
        int sbx = blockIdx.x - 32;           // 0..2047
        int qid0 = sbx * 32;                 // same (b,h) within the group
        int b = qid0 >> 15;
        int h = (qid0 >> 11) & 15;
        int i0 = qid0 & 2047;

        // stage 16 selected k/v rows once (threads 0..255)
        if (tid < 256) {
            int key = tid >> 4;
            int d0  = (tid & 15) * 4;
            int kj = topk[b * Kk + key];
            const __half* kr = qkv + (size_t)(b * Ss + kj) * QKVN + 1024 + h * Dh + d0;
            const __half* vr = kr + 1024;
            __half2 k0 = *(const __half2*)kr, k1 = *(const __half2*)(kr + 2);
            __half2 v0 = *(const __half2*)vr, v1 = *(const __half2*)(vr + 2);
            float2 kf0 = __half22float2(k0), kf1 = __half22float2(k1);
            float2 vf0 = __half22float2(v0), vf1 = __half22float2(v1);
            ks[key * 68 + d0 + 0] = kf0.x; ks[key * 68 + d0 + 1] = kf0.y;
            ks[key * 68 + d0 + 2] = kf1.x; ks[key * 68 + d0 + 3] = kf1.y;
            vs[key * 68 + d0 + 0] = vf0.x; vs[key * 68 + d0 + 1] = vf0.y;
            vs[key * 68 + d0 + 2] = vf1.x; vs[key * 68 + d0 + 3] = vf1.y;
        }
        __syncthreads();

#pragma unroll 1
        for (int r = 0; r < 2; r++) {
            int i = i0 + r * 16 + w;
            // stage this warp's q row (own slot; warp-local)
            const __half* qr = qkv + (size_t)(b * Ss + i) * QKVN + h * Dh;
            qs[w * 64 + lane]      = __half2float(qr[lane]);
            qs[w * 64 + lane + 32] = __half2float(qr[lane + 32]);
            __syncwarp();

            if (!sel[b * Ss + i]) {
                float score = -INFINITY;
                if (lane < 16) {
                    float s = 0.f;
#pragma unroll
                    for (int d = 0; d < 64; d++) s += qs[w * 64 + d] * ks[lane * 68 + d];
                    score = s * 0.125f;
                }
                float m = score;
#pragma unroll
                for (int o = 16; o > 0; o >>= 1)
                    m = fmaxf(m, __shfl_xor_sync(0xffffffffu, m, o));
                float e = (lane < 16) ? expf(score - m) : 0.f;
                float ssum = e;
#pragma unroll
                for (int o = 16; o > 0; o >>= 1)
                    ssum += __shfl_xor_sync(0xffffffffu, ssum, o);
                float wgt = e / ssum;

                float acc0 = 0.f, acc1 = 0.f;
#pragma unroll
                for (int j = 0; j < 16; j++) {
                    float wj = __shfl_sync(0xffffffffu, wgt, j);
                    acc0 = fmaf(wj, vs[j * 68 + lane],      acc0);
                    acc1 = fmaf(wj, vs[j * 68 + lane + 32], acc1);
                }
                size_t base = (size_t)(b * Ss + i) * 1024 + h * Dh;
                aatt[base + lane]      = __float2half(acc0);
                aatt[base + lane + 32] = __float2half(acc1);
            }
            __syncwarp();
        }
        return;
    }

    // ---------- dense path: one block per (b,h), 16 warps = 16 queries -------
    int b = blockIdx.x >> 4, h = blockIdx.x & 15;
    int i = topk[b * Kk + w];

    {
        const __half* qr = qkv + (size_t)(b * Ss + i) * QKVN + h * Dh;
        qs[w * 64 + lane]      = __half2float(qr[lane]);
        qs[w * 64 + lane + 32] = __half2float(qr[lane + 32]);
    }

    float m_run = -INFINITY, sum_l = 0.f, acc0 = 0.f, acc1 = 0.f;

#pragma unroll 1
    for (int t = 0; t < 16; ++t) {
        __syncthreads();
        {
            int key = tid >> 2;
            int d0  = (tid & 3) * 16;
            const __half* kr = qkv + (size_t)(b * Ss + t * 128 + key) * QKVN + 1024 + h * Dh + d0;
            const __half* vr = kr + 1024;
#pragma unroll
            for (int u = 0; u < 4; u++) {
                __half2 kp0 = *(const __half2*)(kr + u * 4);
                __half2 kp1 = *(const __half2*)(kr + u * 4 + 2);
                float2 kf0 = __half22float2(kp0), kf1 = __half22float2(kp1);
                int d = d0 + u * 4;
                ks[(d + 0) * 132 + key] = kf0.x;
                ks[(d + 1) * 132 + key] = kf0.y;
                ks[(d + 2) * 132 + key] = kf1.x;
                ks[(d + 3) * 132 + key] = kf1.y;
                __half2 vp0 = *(const __half2*)(vr + u * 4);
                __half2 vp1 = *(const __half2*)(vr + u * 4 + 2);
                float2 vf0 = __half22float2(vp0), vf1 = __half22float2(vp1);
                *(float4*)(vs + key * 64 + d) = make_float4(vf0.x, vf0.y, vf1.x, vf1.y);
            }
        }
        __syncthreads();

        float sc4[4];
        float mloc = -INFINITY;
#pragma unroll
        for (int c = 0; c < 4; c++) {
            int kk = lane + c * 32;
            float s = 0.f;
#pragma unroll
            for (int d = 0; d < 64; d++) s += qs[w * 64 + d] * ks[d * 132 + kk];
            s *= 0.125f;
            sc4[c] = s;
            mloc = fmaxf(mloc, s);
        }
#pragma unroll
        for (int o = 16; o > 0; o >>= 1)
            mloc = fmaxf(mloc, __shfl_xor_sync(0xffffffffu, mloc, o));
        float m_new = fmaxf(m_run, mloc);
        float scale = expf(m_run - m_new);
        acc0 *= scale; acc1 *= scale; sum_l *= scale;
#pragma unroll
        for (int c = 0; c < 4; c++) {
            float wv = expf(sc4[c] - m_new);
            ws[w * 128 + lane + c * 32] = wv;
            sum_l += wv;
        }
        m_run = m_new;
        __syncwarp();
#pragma unroll 4
        for (int j = 0; j < 128; j++) {
            float wj = ws[w * 128 + j];
            acc0 = fmaf(wj, vs[j * 64 + lane],      acc0);
            acc1 = fmaf(wj, vs[j * 64 + lane + 32], acc1);
        }
    }

    float sum = sum_l;
#pragma unroll
    for (int o = 16; o > 0; o >>= 1) sum += __shfl_xor_sync(0xffffffffu, sum, o);
    float inv = 1.f / sum;

    size_t base = (size_t)(b * Ss + i) * 1024 + h * Dh;
    aatt[base + lane]      = __float2half(acc0 * inv);
    aatt[base + lane + 32] = __float2half(acc1 * inv);
}

// ---------------- launcher ---------------------------------------------------
extern "C" void kernel_launch(void* const* d_in, const int* in_sizes, int n_in,
                              void* d_out, int out_size)
{
    const float* x   = (const float*)d_in[0];
    const float* Wq  = (const float*)d_in[1];
    const float* bq  = (const float*)d_in[2];
    const float* Wk  = (const float*)d_in[3];
    const float* bk  = (const float*)d_in[4];
    const float* Wv  = (const float*)d_in[5];
    const float* bv  = (const float*)d_in[6];
    const float* Wo  = (const float*)d_in[7];
    const float* bo  = (const float*)d_in[8];
    const float* Ws1 = (const float*)d_in[9];
    const float* bs1 = (const float*)d_in[10];
    const float* Ws2 = (const float*)d_in[11];
    float* out = (float*)d_out;

    float *hbuf, *impb;
    int *tkb; unsigned char *selb;
    __half *qkvh, *a2x, *aatt, *bqkv, *boh, *bs1h;
    cudaGetSymbolAddress((void**)&qkvh, g_qkvh);
    cudaGetSymbolAddress((void**)&hbuf, g_h);
    cudaGetSymbolAddress((void**)&impb, g_imp);
    cudaGetSymbolAddress((void**)&tkb,  g_topk);
    cudaGetSymbolAddress((void**)&selb, g_sel);
    cudaGetSymbolAddress((void**)&a2x,  g_a2x);
    cudaGetSymbolAddress((void**)&aatt, g_aatt);
    cudaGetSymbolAddress((void**)&bqkv, g_bqkv);
    cudaGetSymbolAddress((void**)&boh,  g_boh);
    cudaGetSymbolAddress((void**)&bs1h, g_bs1h);

    cudaFuncSetAttribute(gemm_tc, cudaFuncAttributeMaxDynamicSharedMemorySize,
                         GT_SMEM_TOTAL);
    cudaFuncSetAttribute(attn_merged, cudaFuncAttributeMaxDynamicSharedMemorySize,
                         AD_SMEM);

    // conversions
    splitA2_kernel<<<(Mrows * Dd) / 256, 256>>>(x, a2x);
    splitWh5_kernel<<<dim3(32, 32, 5), 256>>>(Wq, Wk, Wv, Wo, Ws1, bqkv, boh, bs1h);

    // fused S1 (bx<4, 2-chunk, relu -> fp32 hbuf) + QKV (bx>=4, hi x hi -> fp16 qkv)
    gemm_tc<<<dim3(QKVN / 128 + 4, Mrows / 128), 256, GT_SMEM_TOTAL>>>(
        a2x, bqkv, bs1h, bq, bk, bv, bs1, nullptr, qkvh, hbuf,
        2048, QKVN, 16, 0, 0, 1, 1);

    // indexer + top-k + attention (merged)
    imp_kernel<<<Mrows / 8, 256>>>(hbuf, Ws2, impb);
    topk_kernel<<<Bb, 32>>>(impb, tkb, selb);
    attn_merged<<<32 + (Bb * Hh * Ss) / 32, 512, AD_SMEM>>>(qkvh, tkb, selb, aatt);

    // output projection (hi x hi -> fp32 out)
    gemm_tc<<<dim3(Dd / 128, Mrows / 128), 256, GT_SMEM_TOTAL>>>(
        aatt, boh, nullptr, bo, bo, bo, nullptr, out, nullptr, nullptr,
        1024, Dd, 16, 0, 0, 0, 0);
}